// round 12
// baseline (speedup 1.0000x reference)
#include <cuda_runtime.h>
#include <cuda_bf16.h>
#include <cstdint>
#include <math.h>

#define BATCH 4
#define C 128
#define MID 32
#define HW 64
#define N 4096   // HW*HW

// ---------------- static device scratch ----------------
__device__ float g_Q[BATCH][C][N];
__device__ float g_V[BATCH][C][N];
__device__ __nv_bfloat16 g_QThi[BATCH][N][C];
__device__ __nv_bfloat16 g_QTlo[BATCH][N][C];
__device__ __nv_bfloat16 g_Vhi[BATCH][C][N];
__device__ __nv_bfloat16 g_Vlo[BATCH][C][N];
__device__ __nv_bfloat16 g_W6hi[C][9 * C];
__device__ __nv_bfloat16 g_W6lo[C][9 * C];
__device__ __nv_bfloat16 g_YTh[BATCH][N][C];
__device__ __nv_bfloat16 g_YTl[BATCH][N][C];
__device__ float g_invnorm[BATCH][N];
__device__ float g_wmap[BATCH][N];
__device__ float g_bmap[BATCH][N];
__device__ float g_off[BATCH][N];
__device__ float g_smax[BATCH][N];
__device__ float g_sinv[BATCH][N];
__device__ float g_L[BATCH][N][N];
__device__ float g_psum[BATCH][32][N];
__device__ float g_pmx[BATCH][16][N];
__device__ float g_psm[BATCH][16][N];

// ---------------- helpers ----------------
__device__ __forceinline__ uint32_t smem_u32(const void* p) {
    uint32_t a;
    asm("{ .reg .u64 t; cvta.to.shared.u64 t, %1; cvt.u32.u64 %0, t; }" : "=r"(a) : "l"(p));
    return a;
}
__device__ __forceinline__ void ldsm_x4(uint32_t* r, uint32_t addr) {
    asm volatile("ldmatrix.sync.aligned.m8n8.x4.shared.b16 {%0,%1,%2,%3}, [%4];"
                 : "=r"(r[0]), "=r"(r[1]), "=r"(r[2]), "=r"(r[3]) : "r"(addr));
}
__device__ __forceinline__ void mma_bf16(float* d, const uint32_t* a, const uint32_t* b) {
    asm volatile(
        "mma.sync.aligned.m16n8k16.row.col.f32.bf16.bf16.f32 "
        "{%0,%1,%2,%3}, {%4,%5,%6,%7}, {%8,%9}, {%0,%1,%2,%3};"
        : "+f"(d[0]), "+f"(d[1]), "+f"(d[2]), "+f"(d[3])
        : "r"(a[0]), "r"(a[1]), "r"(a[2]), "r"(a[3]), "r"(b[0]), "r"(b[1]));
}
__device__ __forceinline__ void cpa16(uint32_t dst, const void* src) {
    asm volatile("cp.async.cg.shared.global [%0], [%1], 16;" :: "r"(dst), "l"(src));
}
#define CPA_COMMIT() asm volatile("cp.async.commit_group;" ::: "memory")
#define CPA_WAIT1() asm volatile("cp.async.wait_group 1;" ::: "memory")
#define CPA_WAIT0() asm volatile("cp.async.wait_group 0;" ::: "memory")

#define TP5 72
#define T5B (128 * TP5 * 2)                // 18432

#define K3_AUX (4 * T5B)                   // 73728
#define K3_SMEM_BYTES (K3_AUX + 3072)      // 76800 -> 2 CTAs/SM

#define K5_LR (4 * T5B)                    // 73728
#define K5_B  (K5_LR + 65536)              // 139264
#define K5_AUX (K5_B + 2 * T5B)            // 176128
#define K5_SMEM_BYTES (K5_AUX + 1536)      // 177664

#define K6_SMEM_BYTES (8 * T5B)            // 147456

// ============================================================================
// K1: Q/V 1x1 convs (+ V as bf16 hi/lo)
// ============================================================================
__global__ void k1_qv(const float* __restrict__ x,
                      const float* __restrict__ qw, const float* __restrict__ qb,
                      const float* __restrict__ vw, const float* __restrict__ vb) {
    const int b = blockIdx.y;
    const int which = blockIdx.z;
    const float* W = which ? vw : qw;
    const float* bias = which ? vb : qb;
    float* out = which ? &g_V[b][0][0] : &g_Q[b][0][0];
    const int n0 = blockIdx.x * 128;
    const float* xb = x + (size_t)b * C * N;

    __shared__ float As[16][128];
    __shared__ float Bs[16][128];
    const int tid = threadIdx.x;
    const int tx = tid & 15, ty = tid >> 4;

    float acc[8][8];
#pragma unroll
    for (int i = 0; i < 8; i++)
#pragma unroll
        for (int j = 0; j < 8; j++) acc[i][j] = 0.f;

    for (int k0 = 0; k0 < 128; k0 += 16) {
        {
            int o = tid >> 1;
            int kb = (tid & 1) * 8;
            float4 a0 = *(const float4*)(W + o * 128 + k0 + kb);
            float4 a1 = *(const float4*)(W + o * 128 + k0 + kb + 4);
            As[kb + 0][o] = a0.x; As[kb + 1][o] = a0.y; As[kb + 2][o] = a0.z; As[kb + 3][o] = a0.w;
            As[kb + 4][o] = a1.x; As[kb + 5][o] = a1.y; As[kb + 6][o] = a1.z; As[kb + 7][o] = a1.w;
        }
        {
            int kk = tid >> 4;
            int nn = (tid & 15) * 8;
            *(float4*)&Bs[kk][nn]     = *(const float4*)(xb + (size_t)(k0 + kk) * N + n0 + nn);
            *(float4*)&Bs[kk][nn + 4] = *(const float4*)(xb + (size_t)(k0 + kk) * N + n0 + nn + 4);
        }
        __syncthreads();
#pragma unroll
        for (int kk = 0; kk < 16; kk++) {
            float ra[8], rb[8];
            *(float4*)&ra[0] = *(const float4*)&As[kk][ty * 8];
            *(float4*)&ra[4] = *(const float4*)&As[kk][ty * 8 + 4];
            *(float4*)&rb[0] = *(const float4*)&Bs[kk][tx * 8];
            *(float4*)&rb[4] = *(const float4*)&Bs[kk][tx * 8 + 4];
#pragma unroll
            for (int i = 0; i < 8; i++)
#pragma unroll
                for (int j = 0; j < 8; j++)
                    acc[i][j] = fmaf(ra[i], rb[j], acc[i][j]);
        }
        __syncthreads();
    }
#pragma unroll
    for (int i = 0; i < 8; i++) {
        int o = ty * 8 + i;
        float bo = bias[o];
        float r[8];
#pragma unroll
        for (int j = 0; j < 8; j++) r[j] = acc[i][j] + bo;
        *(float4*)(out + (size_t)o * N + n0 + tx * 8)     = *(float4*)&r[0];
        *(float4*)(out + (size_t)o * N + n0 + tx * 8 + 4) = *(float4*)&r[4];
        if (which) {
            uint32_t whi[4], wlo[4];
#pragma unroll
            for (int p = 0; p < 4; p++) {
                __nv_bfloat16 h0 = __float2bfloat16(r[2 * p]);
                __nv_bfloat16 h1 = __float2bfloat16(r[2 * p + 1]);
                __nv_bfloat16 l0 = __float2bfloat16(r[2 * p] - __bfloat162float(h0));
                __nv_bfloat16 l1 = __float2bfloat16(r[2 * p + 1] - __bfloat162float(h1));
                whi[p] = (uint32_t)__bfloat16_as_ushort(h0) | ((uint32_t)__bfloat16_as_ushort(h1) << 16);
                wlo[p] = (uint32_t)__bfloat16_as_ushort(l0) | ((uint32_t)__bfloat16_as_ushort(l1) << 16);
            }
            uint4 vh; vh.x = whi[0]; vh.y = whi[1]; vh.z = whi[2]; vh.w = whi[3];
            uint4 vl; vl.x = wlo[0]; vl.y = wlo[1]; vl.z = wlo[2]; vl.w = wlo[3];
            *(uint4*)&g_Vhi[b][o][n0 + tx * 8] = vh;
            *(uint4*)&g_Vlo[b][o][n0 + tx * 8] = vl;
        }
    }
}

// ============================================================================
// K1t: transpose Q -> QT bf16 hi/lo
// ============================================================================
__global__ void k1t_transpose() {
    __shared__ float s[32][33];
    const int b = blockIdx.z;
    const int c0 = blockIdx.y * 32;
    const int n0 = blockIdx.x * 32;
    const int tid = threadIdx.x;
    const int tx = tid & 31, ty = tid >> 5;

#pragma unroll
    for (int p = 0; p < 4; p++)
        s[ty + 8 * p][tx] = g_Q[b][c0 + ty + 8 * p][n0 + tx];
    __syncthreads();
#pragma unroll
    for (int p = 0; p < 4; p++) {
        int r = ty + 8 * p;
        float v = s[tx][r];
        __nv_bfloat16 hi = __float2bfloat16(v);
        __nv_bfloat16 lo = __float2bfloat16(v - __bfloat162float(hi));
        g_QThi[b][n0 + r][c0 + tx] = hi;
        g_QTlo[b][n0 + r][c0 + tx] = lo;
    }
}

// ============================================================================
// K6w: reshape conv weights
// ============================================================================
__global__ void k6w_prep(const float* __restrict__ linw) {
    int idx = blockIdx.x * 256 + threadIdx.x;
    if (idx < C * 9 * C) {
        int o = idx / (9 * C);
        int k = idx % (9 * C);
        int t = k >> 7;
        int ci = k & 127;
        float w = linw[(size_t)(o * C + ci) * 9 + t];
        __nv_bfloat16 hi = __float2bfloat16(w);
        __nv_bfloat16 lo = __float2bfloat16(w - __bfloat162float(hi));
        g_W6hi[o][k] = hi;
        g_W6lo[o][k] = lo;
    }
}

// ============================================================================
// K2: heads, split across z (round-10 form)
// ============================================================================
__global__ void k2_heads(const float* __restrict__ lw1w, const float* __restrict__ lw1b,
                         const float* __restrict__ lw2w, const float* __restrict__ lw2b,
                         const float* __restrict__ bw1w, const float* __restrict__ bw1b,
                         const float* __restrict__ bw2w, const float* __restrict__ bw2b) {
    __shared__ float s_w1[MID][C];
    const int b = blockIdx.y;
    const int which = blockIdx.z;
    const int n = blockIdx.x * 256 + threadIdx.x;
    const float* w1 = which ? bw1w : lw1w;
    const float* b1 = which ? bw1b : lw1b;
    const float* w2 = which ? bw2w : lw2w;
    const float* b2 = which ? bw2b : lw2b;
    for (int e = threadIdx.x; e < MID * C; e += 256)
        s_w1[e / C][e % C] = w1[e];
    __syncthreads();

    float h[MID];
#pragma unroll
    for (int k = 0; k < MID; k++) h[k] = 0.f;
    float sq = 0.f;
#pragma unroll 4
    for (int c = 0; c < C; c++) {
        float q = g_Q[b][c][n];
        sq = fmaf(q, q, sq);
#pragma unroll
        for (int k = 0; k < MID; k++)
            h[k] = fmaf(s_w1[k][c], q, h[k]);
    }
    float v = b2[0];
#pragma unroll
    for (int k = 0; k < MID; k++) {
        float t = h[k] + b1[k];
        t = (t >= 0.f) ? t : 0.2f * t;
        v = fmaf(w2[k], t, v);
    }
    if (which) {
        g_bmap[b][n] = v;
    } else {
        g_wmap[b][n] = v;
        g_invnorm[b][n] = 1.0f / fmaxf(sqrtf(sq), 1e-4f);
    }
}

// ============================================================================
// K3 (mma.sync): symmetric logits, 64-wide K chunks, 2 CTAs/SM (round-10 form)
// ============================================================================
__global__ void __launch_bounds__(256, 2) k3_mma() {
    extern __shared__ char smem[];
    const uint32_t sb = smem_u32(smem);
    const int tid = threadIdx.x;
    const int wid = tid >> 5;
    const int lane = tid & 31;

    const int b = blockIdx.y;
    int rem = blockIdx.x;
    int it = 0;
    while (rem >= 32 - it) { rem -= 32 - it; it++; }
    const int jt = it + rem;
    const int n0 = it * 128;
    const int m0 = jt * 128;
    const bool diag = (it == jt);

    float* s_invn = (float*)(smem + K3_AUX);
    float* s_invm = (float*)(smem + K3_AUX + 512);
    if (tid < 128)      s_invn[tid]       = g_invnorm[b][n0 + tid];
    else                s_invm[tid - 128] = g_invnorm[b][m0 + tid - 128];

    const int wm = (wid & 1) * 64;
    const int wn = (wid >> 1) * 32;
    const uint32_t aoff = (uint32_t)((lane & 15) * (TP5 * 2) + (lane >> 4) * 16);
    const uint32_t boff = (uint32_t)((((lane >> 4) << 3) + (lane & 7)) * (TP5 * 2)
                                     + ((lane >> 3) & 1) * 16);

    const uint32_t aHiB = sb;
    const uint32_t aLoB = sb + T5B;
    const uint32_t bHiB = diag ? aHiB : (sb + 2 * T5B);
    const uint32_t bLoB = diag ? aLoB : (sb + 3 * T5B);
    const int ntiles = diag ? 2 : 4;

    float d[4][4][4];
#pragma unroll
    for (int mt = 0; mt < 4; mt++)
#pragma unroll
        for (int nt = 0; nt < 4; nt++)
#pragma unroll
            for (int q = 0; q < 4; q++) d[mt][nt][q] = 0.f;

    for (int kc = 0; kc < 2; kc++) {
        const char* srcs[4] = {
            (const char*)&g_QThi[b][n0][kc * 64], (const char*)&g_QTlo[b][n0][kc * 64],
            (const char*)&g_QThi[b][m0][kc * 64], (const char*)&g_QTlo[b][m0][kc * 64] };
        for (int i = tid; i < ntiles * 1024; i += 256) {
            int t = i >> 10;
            int row = (i >> 3) & 127;
            int q = i & 7;
            *(uint4*)(smem + t * T5B + row * (TP5 * 2) + q * 16) =
                *(const uint4*)(srcs[t] + (size_t)row * 256 + q * 16);
        }
        __syncthreads();

#pragma unroll
        for (int ks = 0; ks < 4; ks++) {
            const uint32_t kb2 = ks * 32;
            uint32_t ah[4][4], al[4][4], bh[2][4], bl[2][4];
#pragma unroll
            for (int mt = 0; mt < 4; mt++) {
                uint32_t rowb = (uint32_t)((wm + mt * 16) * (TP5 * 2)) + kb2 + aoff;
                ldsm_x4(ah[mt], aHiB + rowb);
                ldsm_x4(al[mt], aLoB + rowb);
            }
#pragma unroll
            for (int np = 0; np < 2; np++) {
                uint32_t rowb = (uint32_t)((wn + np * 16) * (TP5 * 2)) + kb2 + boff;
                ldsm_x4(bh[np], bHiB + rowb);
                ldsm_x4(bl[np], bLoB + rowb);
            }
#pragma unroll
            for (int mt = 0; mt < 4; mt++)
#pragma unroll
                for (int np = 0; np < 2; np++)
#pragma unroll
                    for (int sub = 0; sub < 2; sub++) {
                        const int nt = np * 2 + sub;
                        mma_bf16(d[mt][nt], ah[mt], &bh[np][sub * 2]);
                        mma_bf16(d[mt][nt], ah[mt], &bl[np][sub * 2]);
                        mma_bf16(d[mt][nt], al[mt], &bh[np][sub * 2]);
                    }
        }
        __syncthreads();
    }

    float* sD = (float*)smem;
    {
        const int g = lane >> 2, tg = lane & 3;
#pragma unroll
        for (int mt = 0; mt < 4; mt++) {
#pragma unroll
            for (int nt = 0; nt < 4; nt++) {
                int row0 = wm + mt * 16 + g;
                int col0 = wn + nt * 8 + 2 * tg;
                sD[row0 * 129 + col0]           = d[mt][nt][0];
                sD[row0 * 129 + col0 + 1]       = d[mt][nt][1];
                sD[(row0 + 8) * 129 + col0]     = d[mt][nt][2];
                sD[(row0 + 8) * 129 + col0 + 1] = d[mt][nt][3];
            }
        }
    }
    __syncthreads();

    float* redA = (float*)(smem + K3_AUX + 1024);
    float* redB = (float*)(smem + K3_AUX + 2048);

    {
        const int row = tid >> 1;
        const int cb = (tid & 1) * 64;
        const float invr = s_invn[row];
        float s2 = 0.f;
        float* dst = &g_L[b][n0 + row][m0];
        for (int c = cb; c < cb + 64; c += 4) {
            float d0 = sD[row * 129 + c + 0];
            float d1 = sD[row * 129 + c + 1];
            float d2 = sD[row * 129 + c + 2];
            float d3 = sD[row * 129 + c + 3];
            s2 += d0 * s_invm[c] + d1 * s_invm[c + 1] + d2 * s_invm[c + 2] + d3 * s_invm[c + 3];
            float4 o; o.x = d0 * invr; o.y = d1 * invr; o.z = d2 * invr; o.w = d3 * invr;
            *(float4*)(dst + c) = o;
        }
        redB[tid] = s2;
    }
    {
        const int col = tid >> 1;
        const int rb = (tid & 1) * 64;
        const float invc = s_invm[col];
        float s1 = 0.f;
        float* dst = &g_L[b][m0 + col][n0];
        for (int r = rb; r < rb + 64; r += 4) {
            float d0 = sD[(r + 0) * 129 + col];
            float d1 = sD[(r + 1) * 129 + col];
            float d2 = sD[(r + 2) * 129 + col];
            float d3 = sD[(r + 3) * 129 + col];
            s1 += d0 * s_invn[r] + d1 * s_invn[r + 1] + d2 * s_invn[r + 2] + d3 * s_invn[r + 3];
            if (!diag) {
                float4 o; o.x = d0 * invc; o.y = d1 * invc; o.z = d2 * invc; o.w = d3 * invc;
                *(float4*)(dst + r) = o;
            }
        }
        redA[tid] = s1;
    }
    __syncthreads();
    if (tid < 128) {
        g_psum[b][it][m0 + tid] = redA[2 * tid] + redA[2 * tid + 1];
        if (!diag)
            g_psum[b][jt][n0 + tid] = redB[2 * tid] + redB[2 * tid + 1];
    }
}

// ============================================================================
// K4b: partial online max/sum-exp, 8 independent chains (MLP=8)
// ============================================================================
__global__ void k4b_partial() {
    const int b = blockIdx.z;
    const int chunk = blockIdx.y;
    const int m = blockIdx.x * 256 + threadIdx.x;

    float ps = 0.f;
#pragma unroll
    for (int t = 0; t < 32; t++) ps += g_psum[b][t][m];
    const float mean = ps * (1.0f / N);
    const float off = g_bmap[b][m] - mean * g_wmap[b][m];
    if (chunk == 0) g_off[b][m] = off;

    const int nbase = chunk * 256;
    float mx[8], ss[8];
#pragma unroll
    for (int c = 0; c < 8; c++) { mx[c] = -1e30f; ss[c] = 0.f; }

#define CHAIN(MX, S, L) { float sp = fmaxf((L) + off, 0.f); float z = (L) * sp; \
    if (z <= MX) { S += __expf(z - MX); } else { S = S * __expf(MX - z) + 1.f; MX = z; } }

#pragma unroll 2
    for (int r = 0; r < 256; r += 8) {
        float l[8];
#pragma unroll
        for (int c = 0; c < 8; c++) l[c] = g_L[b][nbase + r + c][m];
#pragma unroll
        for (int c = 0; c < 8; c++) CHAIN(mx[c], ss[c], l[c]);
    }
#undef CHAIN
    // merge 8 chains
    float M = mx[0];
#pragma unroll
    for (int c = 1; c < 8; c++) M = fmaxf(M, mx[c]);
    float S = 0.f;
#pragma unroll
    for (int c = 0; c < 8; c++) S += ss[c] * __expf(mx[c] - M);
    g_pmx[b][chunk][m] = M;
    g_psm[b][chunk][m] = S;
}

__global__ void k4c_final() {
    const int b = blockIdx.y;
    const int m = blockIdx.x * 256 + threadIdx.x;
    float M = g_pmx[b][0][m];
    float S = g_psm[b][0][m];
#pragma unroll
    for (int t = 1; t < 16; t++) {
        float m2 = g_pmx[b][t][m], s2 = g_psm[b][t][m];
        float Mn = fmaxf(M, m2);
        S = S * __expf(M - Mn) + s2 * __expf(m2 - Mn);
        M = Mn;
    }
    g_smax[b][m] = M;
    g_sinv[b][m] = 1.0f / S;
}

// ============================================================================
// K5 (mma.sync + cp.async pipeline): Y = V @ attn(L)  [round-10 winner]
// ============================================================================
__global__ void __launch_bounds__(256, 1) k5_mma() {
    extern __shared__ char smem[];
    const uint32_t sb = smem_u32(smem);
    const int tid = threadIdx.x;
    const int wid = tid >> 5;
    const int lane = tid & 31;
    const int b = blockIdx.y;
    const int m0 = blockIdx.x * 128;

    float* p_off = (float*)(smem + K5_AUX);
    float* p_mx  = (float*)(smem + K5_AUX + 512);
    float* p_si  = (float*)(smem + K5_AUX + 1024);
    if (tid < 128) {
        int m = m0 + tid;
        p_off[tid] = g_off[b][m];
        p_mx[tid]  = g_smax[b][m];
        p_si[tid]  = g_sinv[b][m];
    }

    const int wm = (wid & 1) * 64;
    const int wn = (wid >> 1) * 32;
    const uint32_t aoff = (uint32_t)((lane & 15) * (TP5 * 2) + (lane >> 4) * 16);
    const uint32_t boff = (uint32_t)((((lane >> 4) << 3) + (lane & 7)) * (TP5 * 2)
                                     + ((lane >> 3) & 1) * 16);

    const int mm0 = (tid & 31) * 4;
    const int kk0 = (tid >> 5) * 8;

    float d[4][4][4];
#pragma unroll
    for (int mt = 0; mt < 4; mt++)
#pragma unroll
        for (int nt = 0; nt < 4; nt++)
#pragma unroll
            for (int q = 0; q < 4; q++) d[mt][nt][q] = 0.f;

#define K5_ISSUE(BUFI, NBASE) do {                                               \
        uint32_t abase = sb + (BUFI) * (2 * T5B);                                \
        for (int i = tid; i < 1024; i += 256) {                                  \
            int r = i >> 3, q = i & 7;                                           \
            cpa16(abase + r * (TP5 * 2) + q * 16,                                \
                  (const char*)&g_Vhi[b][r][NBASE] + q * 16);                    \
            cpa16(abase + T5B + r * (TP5 * 2) + q * 16,                          \
                  (const char*)&g_Vlo[b][r][NBASE] + q * 16);                    \
        }                                                                        \
        uint32_t lbase = sb + K5_LR + (BUFI) * 32768;                            \
        for (int i = tid; i < 2048; i += 256) {                                  \
            int kk = i >> 5, q = i & 31;                                         \
            cpa16(lbase + kk * 512 + q * 16,                                     \
                  (const char*)&g_L[b][NBASE + kk][m0] + q * 16);                \
        }                                                                        \
    } while (0)

    K5_ISSUE(0, 0);
    CPA_COMMIT();

    for (int ic = 0; ic < 64; ic++) {
        const int cur = ic & 1;
        if (ic + 1 < 64) {
            K5_ISSUE(cur ^ 1, (ic + 1) * 64);
            CPA_COMMIT();
            CPA_WAIT1();
        } else {
            CPA_WAIT0();
        }
        __syncthreads();

        {
            const float* Lr = (const float*)(smem + K5_LR + cur * 32768);
            uint32_t whi[4][4], wlo[4][4];
#pragma unroll
            for (int j = 0; j < 4; j++)
#pragma unroll
                for (int p = 0; p < 4; p++) { whi[j][p] = 0u; wlo[j][p] = 0u; }
#pragma unroll
            for (int kk = 0; kk < 8; kk++) {
                float4 l4 = *(const float4*)(Lr + (kk0 + kk) * 128 + mm0);
                float ls[4] = {l4.x, l4.y, l4.z, l4.w};
#pragma unroll
                for (int j = 0; j < 4; j++) {
                    int m = mm0 + j;
                    float l = ls[j];
                    float sp = fmaxf(l + p_off[m], 0.f);
                    float a;
                    if (sp > 0.f)
                        a = fmaxf(__expf(l * sp - p_mx[m]) * p_si[m], 1e-8f);
                    else
                        a = 1e-8f;
                    __nv_bfloat16 h = __float2bfloat16(a);
                    __nv_bfloat16 lo = __float2bfloat16(a - __bfloat162float(h));
                    uint32_t sh = (uint32_t)(kk & 1) * 16;
                    whi[j][kk >> 1] |= (uint32_t)__bfloat16_as_ushort(h) << sh;
                    wlo[j][kk >> 1] |= (uint32_t)__bfloat16_as_ushort(lo) << sh;
                }
            }
#pragma unroll
            for (int j = 0; j < 4; j++) {
                uint4 vh; vh.x = whi[j][0]; vh.y = whi[j][1]; vh.z = whi[j][2]; vh.w = whi[j][3];
                uint4 vl; vl.x = wlo[j][0]; vl.y = wlo[j][1]; vl.z = wlo[j][2]; vl.w = wlo[j][3];
                *(uint4*)(smem + K5_B + (mm0 + j) * (TP5 * 2) + kk0 * 2) = vh;
                *(uint4*)(smem + K5_B + T5B + (mm0 + j) * (TP5 * 2) + kk0 * 2) = vl;
            }
        }
        __syncthreads();

        const uint32_t abase = sb + cur * (2 * T5B);
#pragma unroll
        for (int ks = 0; ks < 4; ks++) {
            const uint32_t kb2 = ks * 32;
            uint32_t ah[4][4], al[4][4], bh[2][4], bl[2][4];
#pragma unroll
            for (int mt = 0; mt < 4; mt++) {
                uint32_t rowb = (uint32_t)((wm + mt * 16) * (TP5 * 2)) + kb2 + aoff;
                ldsm_x4(ah[mt], abase + rowb);
                ldsm_x4(al[mt], abase + T5B + rowb);
            }
#pragma unroll
            for (int np = 0; np < 2; np++) {
                uint32_t rowb = (uint32_t)((wn + np * 16) * (TP5 * 2)) + kb2 + boff;
                ldsm_x4(bh[np], sb + K5_B + rowb);
                ldsm_x4(bl[np], sb + K5_B + T5B + rowb);
            }
#pragma unroll
            for (int mt = 0; mt < 4; mt++)
#pragma unroll
                for (int np = 0; np < 2; np++)
#pragma unroll
                    for (int sub = 0; sub < 2; sub++) {
                        const int nt = np * 2 + sub;
                        mma_bf16(d[mt][nt], ah[mt], &bh[np][sub * 2]);
                        mma_bf16(d[mt][nt], ah[mt], &bl[np][sub * 2]);
                        mma_bf16(d[mt][nt], al[mt], &bh[np][sub * 2]);
                    }
        }
        __syncthreads();
    }
#undef K5_ISSUE

    float* sD = (float*)smem;
    {
        const int g = lane >> 2, tg = lane & 3;
#pragma unroll
        for (int mt = 0; mt < 4; mt++) {
#pragma unroll
            for (int nt = 0; nt < 4; nt++) {
                int row0 = wm + mt * 16 + g;
                int col0 = wn + nt * 8 + 2 * tg;
                sD[row0 * 129 + col0]           = d[mt][nt][0];
                sD[row0 * 129 + col0 + 1]       = d[mt][nt][1];
                sD[(row0 + 8) * 129 + col0]     = d[mt][nt][2];
                sD[(row0 + 8) * 129 + col0 + 1] = d[mt][nt][3];
            }
        }
    }
    __syncthreads();
    {
        const int m = tid >> 1;
        const int cb = (tid & 1) * 64;
        uint32_t hibuf[32], lobuf[32];
#pragma unroll 8
        for (int u = 0; u < 32; u++) {
            float v0 = sD[(cb + 2 * u) * 129 + m];
            float v1 = sD[(cb + 2 * u + 1) * 129 + m];
            __nv_bfloat16 h0 = __float2bfloat16(v0);
            __nv_bfloat16 h1 = __float2bfloat16(v1);
            __nv_bfloat16 l0 = __float2bfloat16(v0 - __bfloat162float(h0));
            __nv_bfloat16 l1 = __float2bfloat16(v1 - __bfloat162float(h1));
            hibuf[u] = (uint32_t)__bfloat16_as_ushort(h0) | ((uint32_t)__bfloat16_as_ushort(h1) << 16);
            lobuf[u] = (uint32_t)__bfloat16_as_ushort(l0) | ((uint32_t)__bfloat16_as_ushort(l1) << 16);
        }
#pragma unroll
        for (int q = 0; q < 8; q++) {
            *(uint4*)&g_YTh[b][m0 + m][cb + q * 8] = *(uint4*)&hibuf[q * 4];
            *(uint4*)&g_YTl[b][m0 + m][cb + q * 8] = *(uint4*)&lobuf[q * 4];
        }
    }
}

// ============================================================================
// K6 (mma.sync + cp.async double buffer): conv3x3 implicit GEMM  [round-10]
// ============================================================================
__global__ void __launch_bounds__(256, 1) k6_mma(const float* __restrict__ linb,
                                                 const float* __restrict__ x,
                                                 float* __restrict__ out) {
    extern __shared__ char smem[];
    const uint32_t sb = smem_u32(smem);
    const int tid = threadIdx.x;
    const int wid = tid >> 5;
    const int lane = tid & 31;
    const int b = blockIdx.y;
    const int p0 = blockIdx.x * 128;

    const int wm = (wid & 1) * 64;
    const int wn = (wid >> 1) * 32;
    const uint32_t aoff = (uint32_t)((lane & 15) * (TP5 * 2) + (lane >> 4) * 16);
    const uint32_t boff = (uint32_t)((((lane >> 4) << 3) + (lane & 7)) * (TP5 * 2)
                                     + ((lane >> 3) & 1) * 16);

    float d[4][4][4];
#pragma unroll
    for (int mt = 0; mt < 4; mt++)
#pragma unroll
        for (int nt = 0; nt < 4; nt++)
#pragma unroll
            for (int q = 0; q < 4; q++) d[mt][nt][q] = 0.f;

#define K6_ISSUE(BUFI, T, CB) do {                                               \
        uint32_t base = sb + (BUFI) * (4 * T5B);                                 \
        for (int i = tid; i < 1024; i += 256) {                                  \
            int r = i >> 3, q = i & 7;                                           \
            cpa16(base + r * (TP5 * 2) + q * 16,                                 \
                  (const char*)&g_W6hi[r][(T) * 128 + (CB)] + q * 16);           \
            cpa16(base + T5B + r * (TP5 * 2) + q * 16,                           \
                  (const char*)&g_W6lo[r][(T) * 128 + (CB)] + q * 16);           \
        }                                                                        \
        {                                                                        \
            int dh = (T) / 3 - 1, dw = (T) % 3 - 1;                              \
            for (int i = tid; i < 1024; i += 256) {                              \
                int r = i >> 3, q = i & 7;                                       \
                int p = p0 + r;                                                  \
                int h = (p >> 6) + dh, w = (p & 63) + dw;                        \
                uint32_t dsth = base + 2 * T5B + r * (TP5 * 2) + q * 16;         \
                uint32_t dstl = base + 3 * T5B + r * (TP5 * 2) + q * 16;         \
                if (h >= 0 && h < HW && w >= 0 && w < HW) {                      \
                    int src = (h << 6) + w;                                      \
                    cpa16(dsth, (const char*)&g_YTh[b][src][CB] + q * 16);       \
                    cpa16(dstl, (const char*)&g_YTl[b][src][CB] + q * 16);       \
                } else {                                                         \
                    uint4 z = make_uint4(0u, 0u, 0u, 0u);                        \
                    *(uint4*)(smem + (BUFI) * (4 * T5B) + 2 * T5B + r * (TP5 * 2) + q * 16) = z; \
                    *(uint4*)(smem + (BUFI) * (4 * T5B) + 3 * T5B + r * (TP5 * 2) + q * 16) = z; \
                }                                                                \
            }                                                                    \
        }                                                                        \
    } while (0)

    K6_ISSUE(0, 0, 0);
    CPA_COMMIT();

    for (int ic = 0; ic < 18; ic++) {
        const int cur = ic & 1;
        if (ic + 1 < 18) {
            K6_ISSUE(cur ^ 1, (ic + 1) >> 1, ((ic + 1) & 1) * 64);
            CPA_COMMIT();
            CPA_WAIT1();
        } else {
            CPA_WAIT0();
        }
        __syncthreads();

        const uint32_t base = sb + cur * (4 * T5B);
#pragma unroll
        for (int ks = 0; ks < 4; ks++) {
            const uint32_t kb2 = ks * 32;
            uint32_t ah[4][4], al[4][4], bh[2][4], bl[2][4];
#pragma unroll
            for (int mt = 0; mt < 4; mt++) {
                uint32_t rowb = (uint32_t)((wm + mt * 16) * (TP5 * 2)) + kb2 + aoff;
                ldsm_x4(ah[mt], base + rowb);
                ldsm_x4(al[mt], base + T5B + rowb);
            }
#pragma unroll
            for (int np = 0; np < 2; np++) {
                uint32_t rowb = (uint32_t)((wn + np * 16) * (TP5 * 2)) + kb2 + boff;
                ldsm_x4(bh[np], base + 2 * T5B + rowb);
                ldsm_x4(bl[np], base + 3 * T5B + rowb);
            }
#pragma unroll
            for (int mt = 0; mt < 4; mt++)
#pragma unroll
                for (int np = 0; np < 2; np++)
#pragma unroll
                    for (int sub = 0; sub < 2; sub++) {
                        const int nt = np * 2 + sub;
                        mma_bf16(d[mt][nt], ah[mt], &bh[np][sub * 2]);
                        mma_bf16(d[mt][nt], ah[mt], &bl[np][sub * 2]);
                        mma_bf16(d[mt][nt], al[mt], &bh[np][sub * 2]);
                    }
        }
        __syncthreads();
    }
#undef K6_ISSUE

    {
        const int g = lane >> 2, tg = lane & 3;
#pragma unroll
        for (int mt = 0; mt < 4; mt++) {
            int o0 = wm + mt * 16 + g;
            float b0 = linb[o0];
            float b1 = linb[o0 + 8];
#pragma unroll
            for (int nt = 0; nt < 4; nt++) {
                int col0 = p0 + wn + nt * 8 + 2 * tg;
                size_t base0 = ((size_t)b * C + o0) * N + col0;
                size_t base1 = ((size_t)b * C + o0 + 8) * N + col0;
                float2 xr0 = *(const float2*)(x + base0);
                float2 xr1 = *(const float2*)(x + base1);
                float v00 = d[mt][nt][0] + b0;
                float v01 = d[mt][nt][1] + b0;
                float v10 = d[mt][nt][2] + b1;
                float v11 = d[mt][nt][3] + b1;
                v00 = (v00 >= 0.f) ? v00 : 0.2f * v00;
                v01 = (v01 >= 0.f) ? v01 : 0.2f * v01;
                v10 = (v10 >= 0.f) ? v10 : 0.2f * v10;
                v11 = (v11 >= 0.f) ? v11 : 0.2f * v11;
                float2 o0v; o0v.x = v00 + xr0.x; o0v.y = v01 + xr0.y;
                float2 o1v; o1v.x = v10 + xr1.x; o1v.y = v11 + xr1.y;
                *(float2*)(out + base0) = o0v;
                *(float2*)(out + base1) = o1v;
            }
        }
    }
}

// ============================================================================
extern "C" void kernel_launch(void* const* d_in, const int* in_sizes, int n_in,
                              void* d_out, int out_size) {
    const float* x     = (const float*)d_in[0];
    const float* q_w   = (const float*)d_in[1];
    const float* q_b   = (const float*)d_in[2];
    const float* v_w   = (const float*)d_in[3];
    const float* v_b   = (const float*)d_in[4];
    const float* lw1_w = (const float*)d_in[5];
    const float* lw1_b = (const float*)d_in[6];
    const float* lw2_w = (const float*)d_in[7];
    const float* lw2_b = (const float*)d_in[8];
    const float* bw1_w = (const float*)d_in[9];
    const float* bw1_b = (const float*)d_in[10];
    const float* bw2_w = (const float*)d_in[11];
    const float* bw2_b = (const float*)d_in[12];
    const float* lin_w = (const float*)d_in[13];
    const float* lin_b = (const float*)d_in[14];
    float* out = (float*)d_out;

    cudaFuncSetAttribute(k3_mma, cudaFuncAttributeMaxDynamicSharedMemorySize, K3_SMEM_BYTES);
    cudaFuncSetAttribute(k5_mma, cudaFuncAttributeMaxDynamicSharedMemorySize, K5_SMEM_BYTES);
    cudaFuncSetAttribute(k6_mma, cudaFuncAttributeMaxDynamicSharedMemorySize, K6_SMEM_BYTES);

    k6w_prep<<<(C * 9 * C + 255) / 256, 256>>>(lin_w);
    k1_qv<<<dim3(N / 128, BATCH, 2), 256>>>(x, q_w, q_b, v_w, v_b);
    k1t_transpose<<<dim3(N / 32, C / 32, BATCH), 256>>>();
    k2_heads<<<dim3(N / 256, BATCH, 2), 256>>>(lw1_w, lw1_b, lw2_w, lw2_b,
                                               bw1_w, bw1_b, bw2_w, bw2_b);
    k3_mma<<<dim3(528, BATCH), 256, K3_SMEM_BYTES>>>();
    k4b_partial<<<dim3(16, 16, BATCH), 256>>>();
    k4c_final<<<dim3(16, BATCH), 256>>>();
    k5_mma<<<dim3(N / 128, BATCH), 256, K5_SMEM_BYTES>>>();
    k6_mma<<<dim3(N / 128, BATCH), 256, K6_SMEM_BYTES>>>(lin_b, x, out);
}

// round 13
// speedup vs baseline: 1.0518x; 1.0518x over previous
#include <cuda_runtime.h>
#include <cuda_bf16.h>
#include <cstdint>
#include <math.h>

#define BATCH 4
#define C 128
#define MID 32
#define HW 64
#define N 4096   // HW*HW

// ---------------- static device scratch ----------------
__device__ float g_Q[BATCH][C][N];
__device__ float g_V[BATCH][C][N];
__device__ __nv_bfloat16 g_QThi[BATCH][N][C];
__device__ __nv_bfloat16 g_QTlo[BATCH][N][C];
__device__ __nv_bfloat16 g_Vhi[BATCH][C][N];
__device__ __nv_bfloat16 g_Vlo[BATCH][C][N];
__device__ __nv_bfloat16 g_W6hi[C][9 * C];
__device__ __nv_bfloat16 g_W6lo[C][9 * C];
__device__ __nv_bfloat16 g_YTh[BATCH][N][C];
__device__ __nv_bfloat16 g_YTl[BATCH][N][C];
__device__ float g_invnorm[BATCH][N];
__device__ float g_wmap[BATCH][N];
__device__ float g_bmap[BATCH][N];
__device__ float g_off[BATCH][N];
__device__ float g_L[BATCH][N][N];
__device__ float g_psum[BATCH][32][N];
__device__ float g_pmx[BATCH][16][N];
__device__ float g_psm[BATCH][16][N];

// ---------------- helpers ----------------
__device__ __forceinline__ uint32_t smem_u32(const void* p) {
    uint32_t a;
    asm("{ .reg .u64 t; cvta.to.shared.u64 t, %1; cvt.u32.u64 %0, t; }" : "=r"(a) : "l"(p));
    return a;
}
__device__ __forceinline__ void ldsm_x4(uint32_t* r, uint32_t addr) {
    asm volatile("ldmatrix.sync.aligned.m8n8.x4.shared.b16 {%0,%1,%2,%3}, [%4];"
                 : "=r"(r[0]), "=r"(r[1]), "=r"(r[2]), "=r"(r[3]) : "r"(addr));
}
__device__ __forceinline__ void mma_bf16(float* d, const uint32_t* a, const uint32_t* b) {
    asm volatile(
        "mma.sync.aligned.m16n8k16.row.col.f32.bf16.bf16.f32 "
        "{%0,%1,%2,%3}, {%4,%5,%6,%7}, {%8,%9}, {%0,%1,%2,%3};"
        : "+f"(d[0]), "+f"(d[1]), "+f"(d[2]), "+f"(d[3])
        : "r"(a[0]), "r"(a[1]), "r"(a[2]), "r"(a[3]), "r"(b[0]), "r"(b[1]));
}
__device__ __forceinline__ void cpa16(uint32_t dst, const void* src) {
    asm volatile("cp.async.cg.shared.global [%0], [%1], 16;" :: "r"(dst), "l"(src));
}
#define CPA_COMMIT() asm volatile("cp.async.commit_group;" ::: "memory")
#define CPA_WAIT1() asm volatile("cp.async.wait_group 1;" ::: "memory")
#define CPA_WAIT0() asm volatile("cp.async.wait_group 0;" ::: "memory")

#define TP5 72
#define T5B (128 * TP5 * 2)                // 18432

#define K3_AUX (4 * T5B)                   // 73728
#define K3_SMEM_BYTES (K3_AUX + 3072)      // 76800 -> 2 CTAs/SM

#define K5_LR (4 * T5B)                    // 73728
#define K5_B  (K5_LR + 65536)              // 139264
#define K5_AUX (K5_B + 2 * T5B)            // 176128
#define K5_SMEM_BYTES (K5_AUX + 1536)      // 177664

#define K6_SMEM_BYTES (8 * T5B)            // 147456

// ============================================================================
// K1: Q/V 1x1 convs (+ V as bf16 hi/lo)
// ============================================================================
__global__ void k1_qv(const float* __restrict__ x,
                      const float* __restrict__ qw, const float* __restrict__ qb,
                      const float* __restrict__ vw, const float* __restrict__ vb) {
    const int b = blockIdx.y;
    const int which = blockIdx.z;
    const float* W = which ? vw : qw;
    const float* bias = which ? vb : qb;
    float* out = which ? &g_V[b][0][0] : &g_Q[b][0][0];
    const int n0 = blockIdx.x * 128;
    const float* xb = x + (size_t)b * C * N;

    __shared__ float As[16][128];
    __shared__ float Bs[16][128];
    const int tid = threadIdx.x;
    const int tx = tid & 15, ty = tid >> 4;

    float acc[8][8];
#pragma unroll
    for (int i = 0; i < 8; i++)
#pragma unroll
        for (int j = 0; j < 8; j++) acc[i][j] = 0.f;

    for (int k0 = 0; k0 < 128; k0 += 16) {
        {
            int o = tid >> 1;
            int kb = (tid & 1) * 8;
            float4 a0 = *(const float4*)(W + o * 128 + k0 + kb);
            float4 a1 = *(const float4*)(W + o * 128 + k0 + kb + 4);
            As[kb + 0][o] = a0.x; As[kb + 1][o] = a0.y; As[kb + 2][o] = a0.z; As[kb + 3][o] = a0.w;
            As[kb + 4][o] = a1.x; As[kb + 5][o] = a1.y; As[kb + 6][o] = a1.z; As[kb + 7][o] = a1.w;
        }
        {
            int kk = tid >> 4;
            int nn = (tid & 15) * 8;
            *(float4*)&Bs[kk][nn]     = *(const float4*)(xb + (size_t)(k0 + kk) * N + n0 + nn);
            *(float4*)&Bs[kk][nn + 4] = *(const float4*)(xb + (size_t)(k0 + kk) * N + n0 + nn + 4);
        }
        __syncthreads();
#pragma unroll
        for (int kk = 0; kk < 16; kk++) {
            float ra[8], rb[8];
            *(float4*)&ra[0] = *(const float4*)&As[kk][ty * 8];
            *(float4*)&ra[4] = *(const float4*)&As[kk][ty * 8 + 4];
            *(float4*)&rb[0] = *(const float4*)&Bs[kk][tx * 8];
            *(float4*)&rb[4] = *(const float4*)&Bs[kk][tx * 8 + 4];
#pragma unroll
            for (int i = 0; i < 8; i++)
#pragma unroll
                for (int j = 0; j < 8; j++)
                    acc[i][j] = fmaf(ra[i], rb[j], acc[i][j]);
        }
        __syncthreads();
    }
#pragma unroll
    for (int i = 0; i < 8; i++) {
        int o = ty * 8 + i;
        float bo = bias[o];
        float r[8];
#pragma unroll
        for (int j = 0; j < 8; j++) r[j] = acc[i][j] + bo;
        *(float4*)(out + (size_t)o * N + n0 + tx * 8)     = *(float4*)&r[0];
        *(float4*)(out + (size_t)o * N + n0 + tx * 8 + 4) = *(float4*)&r[4];
        if (which) {
            uint32_t whi[4], wlo[4];
#pragma unroll
            for (int p = 0; p < 4; p++) {
                __nv_bfloat16 h0 = __float2bfloat16(r[2 * p]);
                __nv_bfloat16 h1 = __float2bfloat16(r[2 * p + 1]);
                __nv_bfloat16 l0 = __float2bfloat16(r[2 * p] - __bfloat162float(h0));
                __nv_bfloat16 l1 = __float2bfloat16(r[2 * p + 1] - __bfloat162float(h1));
                whi[p] = (uint32_t)__bfloat16_as_ushort(h0) | ((uint32_t)__bfloat16_as_ushort(h1) << 16);
                wlo[p] = (uint32_t)__bfloat16_as_ushort(l0) | ((uint32_t)__bfloat16_as_ushort(l1) << 16);
            }
            uint4 vh; vh.x = whi[0]; vh.y = whi[1]; vh.z = whi[2]; vh.w = whi[3];
            uint4 vl; vl.x = wlo[0]; vl.y = wlo[1]; vl.z = wlo[2]; vl.w = wlo[3];
            *(uint4*)&g_Vhi[b][o][n0 + tx * 8] = vh;
            *(uint4*)&g_Vlo[b][o][n0 + tx * 8] = vl;
        }
    }
}

// ============================================================================
// K1t: transpose Q -> QT bf16 hi/lo
// ============================================================================
__global__ void k1t_transpose() {
    __shared__ float s[32][33];
    const int b = blockIdx.z;
    const int c0 = blockIdx.y * 32;
    const int n0 = blockIdx.x * 32;
    const int tid = threadIdx.x;
    const int tx = tid & 31, ty = tid >> 5;

#pragma unroll
    for (int p = 0; p < 4; p++)
        s[ty + 8 * p][tx] = g_Q[b][c0 + ty + 8 * p][n0 + tx];
    __syncthreads();
#pragma unroll
    for (int p = 0; p < 4; p++) {
        int r = ty + 8 * p;
        float v = s[tx][r];
        __nv_bfloat16 hi = __float2bfloat16(v);
        __nv_bfloat16 lo = __float2bfloat16(v - __bfloat162float(hi));
        g_QThi[b][n0 + r][c0 + tx] = hi;
        g_QTlo[b][n0 + r][c0 + tx] = lo;
    }
}

// ============================================================================
// K6w: reshape conv weights
// ============================================================================
__global__ void k6w_prep(const float* __restrict__ linw) {
    int idx = blockIdx.x * 256 + threadIdx.x;
    if (idx < C * 9 * C) {
        int o = idx / (9 * C);
        int k = idx % (9 * C);
        int t = k >> 7;
        int ci = k & 127;
        float w = linw[(size_t)(o * C + ci) * 9 + t];
        __nv_bfloat16 hi = __float2bfloat16(w);
        __nv_bfloat16 lo = __float2bfloat16(w - __bfloat162float(hi));
        g_W6hi[o][k] = hi;
        g_W6lo[o][k] = lo;
    }
}

// ============================================================================
// K2: heads, split across z (round-10 form)
// ============================================================================
__global__ void k2_heads(const float* __restrict__ lw1w, const float* __restrict__ lw1b,
                         const float* __restrict__ lw2w, const float* __restrict__ lw2b,
                         const float* __restrict__ bw1w, const float* __restrict__ bw1b,
                         const float* __restrict__ bw2w, const float* __restrict__ bw2b) {
    __shared__ float s_w1[MID][C];
    const int b = blockIdx.y;
    const int which = blockIdx.z;
    const int n = blockIdx.x * 256 + threadIdx.x;
    const float* w1 = which ? bw1w : lw1w;
    const float* b1 = which ? bw1b : lw1b;
    const float* w2 = which ? bw2w : lw2w;
    const float* b2 = which ? bw2b : lw2b;
    for (int e = threadIdx.x; e < MID * C; e += 256)
        s_w1[e / C][e % C] = w1[e];
    __syncthreads();

    float h[MID];
#pragma unroll
    for (int k = 0; k < MID; k++) h[k] = 0.f;
    float sq = 0.f;
#pragma unroll 4
    for (int c = 0; c < C; c++) {
        float q = g_Q[b][c][n];
        sq = fmaf(q, q, sq);
#pragma unroll
        for (int k = 0; k < MID; k++)
            h[k] = fmaf(s_w1[k][c], q, h[k]);
    }
    float v = b2[0];
#pragma unroll
    for (int k = 0; k < MID; k++) {
        float t = h[k] + b1[k];
        t = (t >= 0.f) ? t : 0.2f * t;
        v = fmaf(w2[k], t, v);
    }
    if (which) {
        g_bmap[b][n] = v;
    } else {
        g_wmap[b][n] = v;
        g_invnorm[b][n] = 1.0f / fmaxf(sqrtf(sq), 1e-4f);
    }
}

// ============================================================================
// K3 (mma.sync): symmetric logits, 64-wide K chunks, 2 CTAs/SM,
// staging via cp.async (L1 bypass) — only change vs round-10.
// ============================================================================
__global__ void __launch_bounds__(256, 2) k3_mma() {
    extern __shared__ char smem[];
    const uint32_t sb = smem_u32(smem);
    const int tid = threadIdx.x;
    const int wid = tid >> 5;
    const int lane = tid & 31;

    const int b = blockIdx.y;
    int rem = blockIdx.x;
    int it = 0;
    while (rem >= 32 - it) { rem -= 32 - it; it++; }
    const int jt = it + rem;
    const int n0 = it * 128;
    const int m0 = jt * 128;
    const bool diag = (it == jt);

    float* s_invn = (float*)(smem + K3_AUX);
    float* s_invm = (float*)(smem + K3_AUX + 512);
    if (tid < 128)      s_invn[tid]       = g_invnorm[b][n0 + tid];
    else                s_invm[tid - 128] = g_invnorm[b][m0 + tid - 128];

    const int wm = (wid & 1) * 64;
    const int wn = (wid >> 1) * 32;
    const uint32_t aoff = (uint32_t)((lane & 15) * (TP5 * 2) + (lane >> 4) * 16);
    const uint32_t boff = (uint32_t)((((lane >> 4) << 3) + (lane & 7)) * (TP5 * 2)
                                     + ((lane >> 3) & 1) * 16);

    const uint32_t aHiB = sb;
    const uint32_t aLoB = sb + T5B;
    const uint32_t bHiB = diag ? aHiB : (sb + 2 * T5B);
    const uint32_t bLoB = diag ? aLoB : (sb + 3 * T5B);
    const int ntiles = diag ? 2 : 4;

    float d[4][4][4];
#pragma unroll
    for (int mt = 0; mt < 4; mt++)
#pragma unroll
        for (int nt = 0; nt < 4; nt++)
#pragma unroll
            for (int q = 0; q < 4; q++) d[mt][nt][q] = 0.f;

    for (int kc = 0; kc < 2; kc++) {
        const char* srcs[4] = {
            (const char*)&g_QThi[b][n0][kc * 64], (const char*)&g_QTlo[b][n0][kc * 64],
            (const char*)&g_QThi[b][m0][kc * 64], (const char*)&g_QTlo[b][m0][kc * 64] };
        for (int i = tid; i < ntiles * 1024; i += 256) {
            int t = i >> 10;
            int row = (i >> 3) & 127;
            int q = i & 7;
            cpa16(sb + t * T5B + row * (TP5 * 2) + q * 16,
                  srcs[t] + (size_t)row * 256 + q * 16);
        }
        CPA_COMMIT();
        CPA_WAIT0();
        __syncthreads();

#pragma unroll
        for (int ks = 0; ks < 4; ks++) {
            const uint32_t kb2 = ks * 32;
            uint32_t ah[4][4], al[4][4], bh[2][4], bl[2][4];
#pragma unroll
            for (int mt = 0; mt < 4; mt++) {
                uint32_t rowb = (uint32_t)((wm + mt * 16) * (TP5 * 2)) + kb2 + aoff;
                ldsm_x4(ah[mt], aHiB + rowb);
                ldsm_x4(al[mt], aLoB + rowb);
            }
#pragma unroll
            for (int np = 0; np < 2; np++) {
                uint32_t rowb = (uint32_t)((wn + np * 16) * (TP5 * 2)) + kb2 + boff;
                ldsm_x4(bh[np], bHiB + rowb);
                ldsm_x4(bl[np], bLoB + rowb);
            }
#pragma unroll
            for (int mt = 0; mt < 4; mt++)
#pragma unroll
                for (int np = 0; np < 2; np++)
#pragma unroll
                    for (int sub = 0; sub < 2; sub++) {
                        const int nt = np * 2 + sub;
                        mma_bf16(d[mt][nt], ah[mt], &bh[np][sub * 2]);
                        mma_bf16(d[mt][nt], ah[mt], &bl[np][sub * 2]);
                        mma_bf16(d[mt][nt], al[mt], &bh[np][sub * 2]);
                    }
        }
        __syncthreads();
    }

    float* sD = (float*)smem;
    {
        const int g = lane >> 2, tg = lane & 3;
#pragma unroll
        for (int mt = 0; mt < 4; mt++) {
#pragma unroll
            for (int nt = 0; nt < 4; nt++) {
                int row0 = wm + mt * 16 + g;
                int col0 = wn + nt * 8 + 2 * tg;
                sD[row0 * 129 + col0]           = d[mt][nt][0];
                sD[row0 * 129 + col0 + 1]       = d[mt][nt][1];
                sD[(row0 + 8) * 129 + col0]     = d[mt][nt][2];
                sD[(row0 + 8) * 129 + col0 + 1] = d[mt][nt][3];
            }
        }
    }
    __syncthreads();

    float* redA = (float*)(smem + K3_AUX + 1024);
    float* redB = (float*)(smem + K3_AUX + 2048);

    {
        const int row = tid >> 1;
        const int cb = (tid & 1) * 64;
        const float invr = s_invn[row];
        float s2 = 0.f;
        float* dst = &g_L[b][n0 + row][m0];
        for (int c = cb; c < cb + 64; c += 4) {
            float d0 = sD[row * 129 + c + 0];
            float d1 = sD[row * 129 + c + 1];
            float d2 = sD[row * 129 + c + 2];
            float d3 = sD[row * 129 + c + 3];
            s2 += d0 * s_invm[c] + d1 * s_invm[c + 1] + d2 * s_invm[c + 2] + d3 * s_invm[c + 3];
            float4 o; o.x = d0 * invr; o.y = d1 * invr; o.z = d2 * invr; o.w = d3 * invr;
            *(float4*)(dst + c) = o;
        }
        redB[tid] = s2;
    }
    {
        const int col = tid >> 1;
        const int rb = (tid & 1) * 64;
        const float invc = s_invm[col];
        float s1 = 0.f;
        float* dst = &g_L[b][m0 + col][n0];
        for (int r = rb; r < rb + 64; r += 4) {
            float d0 = sD[(r + 0) * 129 + col];
            float d1 = sD[(r + 1) * 129 + col];
            float d2 = sD[(r + 2) * 129 + col];
            float d3 = sD[(r + 3) * 129 + col];
            s1 += d0 * s_invn[r] + d1 * s_invn[r + 1] + d2 * s_invn[r + 2] + d3 * s_invn[r + 3];
            if (!diag) {
                float4 o; o.x = d0 * invc; o.y = d1 * invc; o.z = d2 * invc; o.w = d3 * invc;
                *(float4*)(dst + r) = o;
            }
        }
        redA[tid] = s1;
    }
    __syncthreads();
    if (tid < 128) {
        g_psum[b][it][m0 + tid] = redA[2 * tid] + redA[2 * tid + 1];
        if (!diag)
            g_psum[b][jt][n0 + tid] = redB[2 * tid] + redB[2 * tid + 1];
    }
}

// ============================================================================
// K4b: partial online max/sum-exp (round-10 4-chain form)
// ============================================================================
__global__ void k4b_partial() {
    const int b = blockIdx.z;
    const int chunk = blockIdx.y;
    const int m = blockIdx.x * 256 + threadIdx.x;

    float ps = 0.f;
#pragma unroll
    for (int t = 0; t < 32; t++) ps += g_psum[b][t][m];
    const float mean = ps * (1.0f / N);
    const float off = g_bmap[b][m] - mean * g_wmap[b][m];
    if (chunk == 0) g_off[b][m] = off;

    const int nbase = chunk * 256;
    float mx0 = -1e30f, mx1 = -1e30f, mx2 = -1e30f, mx3 = -1e30f;
    float s0 = 0.f, s1 = 0.f, s2 = 0.f, s3 = 0.f;

#define CHAIN(MX, S, L) { float sp = fmaxf((L) + off, 0.f); float z = (L) * sp; \
    if (z <= MX) { S += __expf(z - MX); } else { S = S * __expf(MX - z) + 1.f; MX = z; } }

#pragma unroll 2
    for (int r = 0; r < 256; r += 4) {
        float l0 = g_L[b][nbase + r + 0][m];
        float l1 = g_L[b][nbase + r + 1][m];
        float l2 = g_L[b][nbase + r + 2][m];
        float l3 = g_L[b][nbase + r + 3][m];
        CHAIN(mx0, s0, l0);
        CHAIN(mx1, s1, l1);
        CHAIN(mx2, s2, l2);
        CHAIN(mx3, s3, l3);
    }
#undef CHAIN
    float M = fmaxf(fmaxf(mx0, mx1), fmaxf(mx2, mx3));
    float S = s0 * __expf(mx0 - M) + s1 * __expf(mx1 - M)
            + s2 * __expf(mx2 - M) + s3 * __expf(mx3 - M);
    g_pmx[b][chunk][m] = M;
    g_psm[b][chunk][m] = S;
}

// ============================================================================
// K5 (mma.sync + cp.async pipeline): Y = V @ attn(L)
// k4c merged into prologue (16-way partial merge per m column).
// ============================================================================
__global__ void __launch_bounds__(256, 1) k5_mma() {
    extern __shared__ char smem[];
    const uint32_t sb = smem_u32(smem);
    const int tid = threadIdx.x;
    const int wid = tid >> 5;
    const int lane = tid & 31;
    const int b = blockIdx.y;
    const int m0 = blockIdx.x * 128;

    float* p_off = (float*)(smem + K5_AUX);
    float* p_mx  = (float*)(smem + K5_AUX + 512);
    float* p_si  = (float*)(smem + K5_AUX + 1024);
    if (tid < 128) {
        int m = m0 + tid;
        p_off[tid] = g_off[b][m];
        // merge 16 chunk partials (was k4c)
        float M = g_pmx[b][0][m];
        float S = g_psm[b][0][m];
#pragma unroll
        for (int t = 1; t < 16; t++) {
            float m2 = g_pmx[b][t][m], s2 = g_psm[b][t][m];
            float Mn = fmaxf(M, m2);
            S = S * __expf(M - Mn) + s2 * __expf(m2 - Mn);
            M = Mn;
        }
        p_mx[tid] = M;
        p_si[tid] = 1.0f / S;
    }

    const int wm = (wid & 1) * 64;
    const int wn = (wid >> 1) * 32;
    const uint32_t aoff = (uint32_t)((lane & 15) * (TP5 * 2) + (lane >> 4) * 16);
    const uint32_t boff = (uint32_t)((((lane >> 4) << 3) + (lane & 7)) * (TP5 * 2)
                                     + ((lane >> 3) & 1) * 16);

    const int mm0 = (tid & 31) * 4;
    const int kk0 = (tid >> 5) * 8;

    float d[4][4][4];
#pragma unroll
    for (int mt = 0; mt < 4; mt++)
#pragma unroll
        for (int nt = 0; nt < 4; nt++)
#pragma unroll
            for (int q = 0; q < 4; q++) d[mt][nt][q] = 0.f;

#define K5_ISSUE(BUFI, NBASE) do {                                               \
        uint32_t abase = sb + (BUFI) * (2 * T5B);                                \
        for (int i = tid; i < 1024; i += 256) {                                  \
            int r = i >> 3, q = i & 7;                                           \
            cpa16(abase + r * (TP5 * 2) + q * 16,                                \
                  (const char*)&g_Vhi[b][r][NBASE] + q * 16);                    \
            cpa16(abase + T5B + r * (TP5 * 2) + q * 16,                          \
                  (const char*)&g_Vlo[b][r][NBASE] + q * 16);                    \
        }                                                                        \
        uint32_t lbase = sb + K5_LR + (BUFI) * 32768;                            \
        for (int i = tid; i < 2048; i += 256) {                                  \
            int kk = i >> 5, q = i & 31;                                         \
            cpa16(lbase + kk * 512 + q * 16,                                     \
                  (const char*)&g_L[b][NBASE + kk][m0] + q * 16);                \
        }                                                                        \
    } while (0)

    K5_ISSUE(0, 0);
    CPA_COMMIT();

    for (int ic = 0; ic < 64; ic++) {
        const int cur = ic & 1;
        if (ic + 1 < 64) {
            K5_ISSUE(cur ^ 1, (ic + 1) * 64);
            CPA_COMMIT();
            CPA_WAIT1();
        } else {
            CPA_WAIT0();
        }
        __syncthreads();

        {
            const float* Lr = (const float*)(smem + K5_LR + cur * 32768);
            uint32_t whi[4][4], wlo[4][4];
#pragma unroll
            for (int j = 0; j < 4; j++)
#pragma unroll
                for (int p = 0; p < 4; p++) { whi[j][p] = 0u; wlo[j][p] = 0u; }
#pragma unroll
            for (int kk = 0; kk < 8; kk++) {
                float4 l4 = *(const float4*)(Lr + (kk0 + kk) * 128 + mm0);
                float ls[4] = {l4.x, l4.y, l4.z, l4.w};
#pragma unroll
                for (int j = 0; j < 4; j++) {
                    int m = mm0 + j;
                    float l = ls[j];
                    float sp = fmaxf(l + p_off[m], 0.f);
                    float a;
                    if (sp > 0.f)
                        a = fmaxf(__expf(l * sp - p_mx[m]) * p_si[m], 1e-8f);
                    else
                        a = 1e-8f;
                    __nv_bfloat16 h = __float2bfloat16(a);
                    __nv_bfloat16 lo = __float2bfloat16(a - __bfloat162float(h));
                    uint32_t sh = (uint32_t)(kk & 1) * 16;
                    whi[j][kk >> 1] |= (uint32_t)__bfloat16_as_ushort(h) << sh;
                    wlo[j][kk >> 1] |= (uint32_t)__bfloat16_as_ushort(lo) << sh;
                }
            }
#pragma unroll
            for (int j = 0; j < 4; j++) {
                uint4 vh; vh.x = whi[j][0]; vh.y = whi[j][1]; vh.z = whi[j][2]; vh.w = whi[j][3];
                uint4 vl; vl.x = wlo[j][0]; vl.y = wlo[j][1]; vl.z = wlo[j][2]; vl.w = wlo[j][3];
                *(uint4*)(smem + K5_B + (mm0 + j) * (TP5 * 2) + kk0 * 2) = vh;
                *(uint4*)(smem + K5_B + T5B + (mm0 + j) * (TP5 * 2) + kk0 * 2) = vl;
            }
        }
        __syncthreads();

        const uint32_t abase = sb + cur * (2 * T5B);
#pragma unroll
        for (int ks = 0; ks < 4; ks++) {
            const uint32_t kb2 = ks * 32;
            uint32_t ah[4][4], al[4][4], bh[2][4], bl[2][4];
#pragma unroll
            for (int mt = 0; mt < 4; mt++) {
                uint32_t rowb = (uint32_t)((wm + mt * 16) * (TP5 * 2)) + kb2 + aoff;
                ldsm_x4(ah[mt], abase + rowb);
                ldsm_x4(al[mt], abase + T5B + rowb);
            }
#pragma unroll
            for (int np = 0; np < 2; np++) {
                uint32_t rowb = (uint32_t)((wn + np * 16) * (TP5 * 2)) + kb2 + boff;
                ldsm_x4(bh[np], sb + K5_B + rowb);
                ldsm_x4(bl[np], sb + K5_B + T5B + rowb);
            }
#pragma unroll
            for (int mt = 0; mt < 4; mt++)
#pragma unroll
                for (int np = 0; np < 2; np++)
#pragma unroll
                    for (int sub = 0; sub < 2; sub++) {
                        const int nt = np * 2 + sub;
                        mma_bf16(d[mt][nt], ah[mt], &bh[np][sub * 2]);
                        mma_bf16(d[mt][nt], ah[mt], &bl[np][sub * 2]);
                        mma_bf16(d[mt][nt], al[mt], &bh[np][sub * 2]);
                    }
        }
        __syncthreads();
    }
#undef K5_ISSUE

    float* sD = (float*)smem;
    {
        const int g = lane >> 2, tg = lane & 3;
#pragma unroll
        for (int mt = 0; mt < 4; mt++) {
#pragma unroll
            for (int nt = 0; nt < 4; nt++) {
                int row0 = wm + mt * 16 + g;
                int col0 = wn + nt * 8 + 2 * tg;
                sD[row0 * 129 + col0]           = d[mt][nt][0];
                sD[row0 * 129 + col0 + 1]       = d[mt][nt][1];
                sD[(row0 + 8) * 129 + col0]     = d[mt][nt][2];
                sD[(row0 + 8) * 129 + col0 + 1] = d[mt][nt][3];
            }
        }
    }
    __syncthreads();
    {
        const int m = tid >> 1;
        const int cb = (tid & 1) * 64;
        uint32_t hibuf[32], lobuf[32];
#pragma unroll 8
        for (int u = 0; u < 32; u++) {
            float v0 = sD[(cb + 2 * u) * 129 + m];
            float v1 = sD[(cb + 2 * u + 1) * 129 + m];
            __nv_bfloat16 h0 = __float2bfloat16(v0);
            __nv_bfloat16 h1 = __float2bfloat16(v1);
            __nv_bfloat16 l0 = __float2bfloat16(v0 - __bfloat162float(h0));
            __nv_bfloat16 l1 = __float2bfloat16(v1 - __bfloat162float(h1));
            hibuf[u] = (uint32_t)__bfloat16_as_ushort(h0) | ((uint32_t)__bfloat16_as_ushort(h1) << 16);
            lobuf[u] = (uint32_t)__bfloat16_as_ushort(l0) | ((uint32_t)__bfloat16_as_ushort(l1) << 16);
        }
#pragma unroll
        for (int q = 0; q < 8; q++) {
            *(uint4*)&g_YTh[b][m0 + m][cb + q * 8] = *(uint4*)&hibuf[q * 4];
            *(uint4*)&g_YTl[b][m0 + m][cb + q * 8] = *(uint4*)&lobuf[q * 4];
        }
    }
}

// ============================================================================
// K6 (mma.sync + cp.async double buffer): conv3x3 implicit GEMM  [round-10]
// ============================================================================
__global__ void __launch_bounds__(256, 1) k6_mma(const float* __restrict__ linb,
                                                 const float* __restrict__ x,
                                                 float* __restrict__ out) {
    extern __shared__ char smem[];
    const uint32_t sb = smem_u32(smem);
    const int tid = threadIdx.x;
    const int wid = tid >> 5;
    const int lane = tid & 31;
    const int b = blockIdx.y;
    const int p0 = blockIdx.x * 128;

    const int wm = (wid & 1) * 64;
    const int wn = (wid >> 1) * 32;
    const uint32_t aoff = (uint32_t)((lane & 15) * (TP5 * 2) + (lane >> 4) * 16);
    const uint32_t boff = (uint32_t)((((lane >> 4) << 3) + (lane & 7)) * (TP5 * 2)
                                     + ((lane >> 3) & 1) * 16);

    float d[4][4][4];
#pragma unroll
    for (int mt = 0; mt < 4; mt++)
#pragma unroll
        for (int nt = 0; nt < 4; nt++)
#pragma unroll
            for (int q = 0; q < 4; q++) d[mt][nt][q] = 0.f;

#define K6_ISSUE(BUFI, T, CB) do {                                               \
        uint32_t base = sb + (BUFI) * (4 * T5B);                                 \
        for (int i = tid; i < 1024; i += 256) {                                  \
            int r = i >> 3, q = i & 7;                                           \
            cpa16(base + r * (TP5 * 2) + q * 16,                                 \
                  (const char*)&g_W6hi[r][(T) * 128 + (CB)] + q * 16);           \
            cpa16(base + T5B + r * (TP5 * 2) + q * 16,                           \
                  (const char*)&g_W6lo[r][(T) * 128 + (CB)] + q * 16);           \
        }                                                                        \
        {                                                                        \
            int dh = (T) / 3 - 1, dw = (T) % 3 - 1;                              \
            for (int i = tid; i < 1024; i += 256) {                              \
                int r = i >> 3, q = i & 7;                                       \
                int p = p0 + r;                                                  \
                int h = (p >> 6) + dh, w = (p & 63) + dw;                        \
                uint32_t dsth = base + 2 * T5B + r * (TP5 * 2) + q * 16;         \
                uint32_t dstl = base + 3 * T5B + r * (TP5 * 2) + q * 16;         \
                if (h >= 0 && h < HW && w >= 0 && w < HW) {                      \
                    int src = (h << 6) + w;                                      \
                    cpa16(dsth, (const char*)&g_YTh[b][src][CB] + q * 16);       \
                    cpa16(dstl, (const char*)&g_YTl[b][src][CB] + q * 16);       \
                } else {                                                         \
                    uint4 z = make_uint4(0u, 0u, 0u, 0u);                        \
                    *(uint4*)(smem + (BUFI) * (4 * T5B) + 2 * T5B + r * (TP5 * 2) + q * 16) = z; \
                    *(uint4*)(smem + (BUFI) * (4 * T5B) + 3 * T5B + r * (TP5 * 2) + q * 16) = z; \
                }                                                                \
            }                                                                    \
        }                                                                        \
    } while (0)

    K6_ISSUE(0, 0, 0);
    CPA_COMMIT();

    for (int ic = 0; ic < 18; ic++) {
        const int cur = ic & 1;
        if (ic + 1 < 18) {
            K6_ISSUE(cur ^ 1, (ic + 1) >> 1, ((ic + 1) & 1) * 64);
            CPA_COMMIT();
            CPA_WAIT1();
        } else {
            CPA_WAIT0();
        }
        __syncthreads();

        const uint32_t base = sb + cur * (4 * T5B);
#pragma unroll
        for (int ks = 0; ks < 4; ks++) {
            const uint32_t kb2 = ks * 32;
            uint32_t ah[4][4], al[4][4], bh[2][4], bl[2][4];
#pragma unroll
            for (int mt = 0; mt < 4; mt++) {
                uint32_t rowb = (uint32_t)((wm + mt * 16) * (TP5 * 2)) + kb2 + aoff;
                ldsm_x4(ah[mt], base + rowb);
                ldsm_x4(al[mt], base + T5B + rowb);
            }
#pragma unroll
            for (int np = 0; np < 2; np++) {
                uint32_t rowb = (uint32_t)((wn + np * 16) * (TP5 * 2)) + kb2 + boff;
                ldsm_x4(bh[np], base + 2 * T5B + rowb);
                ldsm_x4(bl[np], base + 3 * T5B + rowb);
            }
#pragma unroll
            for (int mt = 0; mt < 4; mt++)
#pragma unroll
                for (int np = 0; np < 2; np++)
#pragma unroll
                    for (int sub = 0; sub < 2; sub++) {
                        const int nt = np * 2 + sub;
                        mma_bf16(d[mt][nt], ah[mt], &bh[np][sub * 2]);
                        mma_bf16(d[mt][nt], ah[mt], &bl[np][sub * 2]);
                        mma_bf16(d[mt][nt], al[mt], &bh[np][sub * 2]);
                    }
        }
        __syncthreads();
    }
#undef K6_ISSUE

    {
        const int g = lane >> 2, tg = lane & 3;
#pragma unroll
        for (int mt = 0; mt < 4; mt++) {
            int o0 = wm + mt * 16 + g;
            float b0 = linb[o0];
            float b1 = linb[o0 + 8];
#pragma unroll
            for (int nt = 0; nt < 4; nt++) {
                int col0 = p0 + wn + nt * 8 + 2 * tg;
                size_t base0 = ((size_t)b * C + o0) * N + col0;
                size_t base1 = ((size_t)b * C + o0 + 8) * N + col0;
                float2 xr0 = *(const float2*)(x + base0);
                float2 xr1 = *(const float2*)(x + base1);
                float v00 = d[mt][nt][0] + b0;
                float v01 = d[mt][nt][1] + b0;
                float v10 = d[mt][nt][2] + b1;
                float v11 = d[mt][nt][3] + b1;
                v00 = (v00 >= 0.f) ? v00 : 0.2f * v00;
                v01 = (v01 >= 0.f) ? v01 : 0.2f * v01;
                v10 = (v10 >= 0.f) ? v10 : 0.2f * v10;
                v11 = (v11 >= 0.f) ? v11 : 0.2f * v11;
                float2 o0v; o0v.x = v00 + xr0.x; o0v.y = v01 + xr0.y;
                float2 o1v; o1v.x = v10 + xr1.x; o1v.y = v11 + xr1.y;
                *(float2*)(out + base0) = o0v;
                *(float2*)(out + base1) = o1v;
            }
        }
    }
}

// ============================================================================
extern "C" void kernel_launch(void* const* d_in, const int* in_sizes, int n_in,
                              void* d_out, int out_size) {
    const float* x     = (const float*)d_in[0];
    const float* q_w   = (const float*)d_in[1];
    const float* q_b   = (const float*)d_in[2];
    const float* v_w   = (const float*)d_in[3];
    const float* v_b   = (const float*)d_in[4];
    const float* lw1_w = (const float*)d_in[5];
    const float* lw1_b = (const float*)d_in[6];
    const float* lw2_w = (const float*)d_in[7];
    const float* lw2_b = (const float*)d_in[8];
    const float* bw1_w = (const float*)d_in[9];
    const float* bw1_b = (const float*)d_in[10];
    const float* bw2_w = (const float*)d_in[11];
    const float* bw2_b = (const float*)d_in[12];
    const float* lin_w = (const float*)d_in[13];
    const float* lin_b = (const float*)d_in[14];
    float* out = (float*)d_out;

    cudaFuncSetAttribute(k3_mma, cudaFuncAttributeMaxDynamicSharedMemorySize, K3_SMEM_BYTES);
    cudaFuncSetAttribute(k5_mma, cudaFuncAttributeMaxDynamicSharedMemorySize, K5_SMEM_BYTES);
    cudaFuncSetAttribute(k6_mma, cudaFuncAttributeMaxDynamicSharedMemorySize, K6_SMEM_BYTES);

    k6w_prep<<<(C * 9 * C + 255) / 256, 256>>>(lin_w);
    k1_qv<<<dim3(N / 128, BATCH, 2), 256>>>(x, q_w, q_b, v_w, v_b);
    k1t_transpose<<<dim3(N / 32, C / 32, BATCH), 256>>>();
    k2_heads<<<dim3(N / 256, BATCH, 2), 256>>>(lw1_w, lw1_b, lw2_w, lw2_b,
                                               bw1_w, bw1_b, bw2_w, bw2_b);
    k3_mma<<<dim3(528, BATCH), 256, K3_SMEM_BYTES>>>();
    k4b_partial<<<dim3(16, 16, BATCH), 256>>>();
    k5_mma<<<dim3(N / 128, BATCH), 256, K5_SMEM_BYTES>>>();
    k6_mma<<<dim3(N / 128, BATCH), 256, K6_SMEM_BYTES>>>(lin_b, x, out);
}

// round 14
// speedup vs baseline: 1.0617x; 1.0093x over previous
#include <cuda_runtime.h>
#include <cuda_bf16.h>
#include <cstdint>
#include <math.h>

#define BATCH 4
#define C 128
#define MID 32
#define HW 64
#define N 4096   // HW*HW

// ---------------- static device scratch ----------------
__device__ float g_Q[BATCH][C][N];
__device__ __nv_bfloat16 g_QThi[BATCH][N][C];
__device__ __nv_bfloat16 g_QTlo[BATCH][N][C];
__device__ __nv_bfloat16 g_Vhi[BATCH][C][N];
__device__ __nv_bfloat16 g_Vlo[BATCH][C][N];
__device__ __nv_bfloat16 g_W6hi[C][9 * C];
__device__ __nv_bfloat16 g_W6lo[C][9 * C];
__device__ __nv_bfloat16 g_YTh[BATCH][N][C];
__device__ __nv_bfloat16 g_YTl[BATCH][N][C];
__device__ float g_invnorm[BATCH][N];
__device__ float g_wmap[BATCH][N];
__device__ float g_bmap[BATCH][N];
__device__ float g_off[BATCH][N];
__device__ float g_L[BATCH][N][N];
__device__ float g_psum[BATCH][32][N];
__device__ float g_pmx[BATCH][16][N];
__device__ float g_psm[BATCH][16][N];

// ---------------- helpers ----------------
__device__ __forceinline__ uint32_t smem_u32(const void* p) {
    uint32_t a;
    asm("{ .reg .u64 t; cvta.to.shared.u64 t, %1; cvt.u32.u64 %0, t; }" : "=r"(a) : "l"(p));
    return a;
}
__device__ __forceinline__ void ldsm_x4(uint32_t* r, uint32_t addr) {
    asm volatile("ldmatrix.sync.aligned.m8n8.x4.shared.b16 {%0,%1,%2,%3}, [%4];"
                 : "=r"(r[0]), "=r"(r[1]), "=r"(r[2]), "=r"(r[3]) : "r"(addr));
}
__device__ __forceinline__ void mma_bf16(float* d, const uint32_t* a, const uint32_t* b) {
    asm volatile(
        "mma.sync.aligned.m16n8k16.row.col.f32.bf16.bf16.f32 "
        "{%0,%1,%2,%3}, {%4,%5,%6,%7}, {%8,%9}, {%0,%1,%2,%3};"
        : "+f"(d[0]), "+f"(d[1]), "+f"(d[2]), "+f"(d[3])
        : "r"(a[0]), "r"(a[1]), "r"(a[2]), "r"(a[3]), "r"(b[0]), "r"(b[1]));
}
__device__ __forceinline__ void cpa16(uint32_t dst, const void* src) {
    asm volatile("cp.async.cg.shared.global [%0], [%1], 16;" :: "r"(dst), "l"(src));
}
#define CPA_COMMIT() asm volatile("cp.async.commit_group;" ::: "memory")
#define CPA_WAIT1() asm volatile("cp.async.wait_group 1;" ::: "memory")
#define CPA_WAIT0() asm volatile("cp.async.wait_group 0;" ::: "memory")

#define TP5 72
#define T5B (128 * TP5 * 2)                // 18432

#define K3_AUX (4 * T5B)                   // 73728
#define K3_SMEM_BYTES (K3_AUX + 3072)      // 76800 -> 2 CTAs/SM

#define K5_LR (4 * T5B)                    // 73728
#define K5_B  (K5_LR + 65536)              // 139264  (two B hi/lo pairs follow)
#define K5_AUX (K5_B + 4 * T5B)            // 212992
#define K5_SMEM_BYTES (K5_AUX + 1536)      // 214528

#define K6_SMEM_BYTES (8 * T5B)            // 147456

// ============================================================================
// K1: Q/V 1x1 convs (V emitted only as bf16 hi/lo; fp32 V store dropped)
// ============================================================================
__global__ void k1_qv(const float* __restrict__ x,
                      const float* __restrict__ qw, const float* __restrict__ qb,
                      const float* __restrict__ vw, const float* __restrict__ vb) {
    const int b = blockIdx.y;
    const int which = blockIdx.z;
    const float* W = which ? vw : qw;
    const float* bias = which ? vb : qb;
    const int n0 = blockIdx.x * 128;
    const float* xb = x + (size_t)b * C * N;

    __shared__ float As[16][128];
    __shared__ float Bs[16][128];
    const int tid = threadIdx.x;
    const int tx = tid & 15, ty = tid >> 4;

    float acc[8][8];
#pragma unroll
    for (int i = 0; i < 8; i++)
#pragma unroll
        for (int j = 0; j < 8; j++) acc[i][j] = 0.f;

    for (int k0 = 0; k0 < 128; k0 += 16) {
        {
            int o = tid >> 1;
            int kb = (tid & 1) * 8;
            float4 a0 = *(const float4*)(W + o * 128 + k0 + kb);
            float4 a1 = *(const float4*)(W + o * 128 + k0 + kb + 4);
            As[kb + 0][o] = a0.x; As[kb + 1][o] = a0.y; As[kb + 2][o] = a0.z; As[kb + 3][o] = a0.w;
            As[kb + 4][o] = a1.x; As[kb + 5][o] = a1.y; As[kb + 6][o] = a1.z; As[kb + 7][o] = a1.w;
        }
        {
            int kk = tid >> 4;
            int nn = (tid & 15) * 8;
            *(float4*)&Bs[kk][nn]     = *(const float4*)(xb + (size_t)(k0 + kk) * N + n0 + nn);
            *(float4*)&Bs[kk][nn + 4] = *(const float4*)(xb + (size_t)(k0 + kk) * N + n0 + nn + 4);
        }
        __syncthreads();
#pragma unroll
        for (int kk = 0; kk < 16; kk++) {
            float ra[8], rb[8];
            *(float4*)&ra[0] = *(const float4*)&As[kk][ty * 8];
            *(float4*)&ra[4] = *(const float4*)&As[kk][ty * 8 + 4];
            *(float4*)&rb[0] = *(const float4*)&Bs[kk][tx * 8];
            *(float4*)&rb[4] = *(const float4*)&Bs[kk][tx * 8 + 4];
#pragma unroll
            for (int i = 0; i < 8; i++)
#pragma unroll
                for (int j = 0; j < 8; j++)
                    acc[i][j] = fmaf(ra[i], rb[j], acc[i][j]);
        }
        __syncthreads();
    }
#pragma unroll
    for (int i = 0; i < 8; i++) {
        int o = ty * 8 + i;
        float bo = bias[o];
        float r[8];
#pragma unroll
        for (int j = 0; j < 8; j++) r[j] = acc[i][j] + bo;
        if (!which) {
            *(float4*)(&g_Q[b][o][n0 + tx * 8])     = *(float4*)&r[0];
            *(float4*)(&g_Q[b][o][n0 + tx * 8 + 4]) = *(float4*)&r[4];
        } else {
            uint32_t whi[4], wlo[4];
#pragma unroll
            for (int p = 0; p < 4; p++) {
                __nv_bfloat16 h0 = __float2bfloat16(r[2 * p]);
                __nv_bfloat16 h1 = __float2bfloat16(r[2 * p + 1]);
                __nv_bfloat16 l0 = __float2bfloat16(r[2 * p] - __bfloat162float(h0));
                __nv_bfloat16 l1 = __float2bfloat16(r[2 * p + 1] - __bfloat162float(h1));
                whi[p] = (uint32_t)__bfloat16_as_ushort(h0) | ((uint32_t)__bfloat16_as_ushort(h1) << 16);
                wlo[p] = (uint32_t)__bfloat16_as_ushort(l0) | ((uint32_t)__bfloat16_as_ushort(l1) << 16);
            }
            uint4 vh; vh.x = whi[0]; vh.y = whi[1]; vh.z = whi[2]; vh.w = whi[3];
            uint4 vl; vl.x = wlo[0]; vl.y = wlo[1]; vl.z = wlo[2]; vl.w = wlo[3];
            *(uint4*)&g_Vhi[b][o][n0 + tx * 8] = vh;
            *(uint4*)&g_Vlo[b][o][n0 + tx * 8] = vl;
        }
    }
}

// ============================================================================
// K1t: transpose Q -> QT bf16 hi/lo
// ============================================================================
__global__ void k1t_transpose() {
    __shared__ float s[32][33];
    const int b = blockIdx.z;
    const int c0 = blockIdx.y * 32;
    const int n0 = blockIdx.x * 32;
    const int tid = threadIdx.x;
    const int tx = tid & 31, ty = tid >> 5;

#pragma unroll
    for (int p = 0; p < 4; p++)
        s[ty + 8 * p][tx] = g_Q[b][c0 + ty + 8 * p][n0 + tx];
    __syncthreads();
#pragma unroll
    for (int p = 0; p < 4; p++) {
        int r = ty + 8 * p;
        float v = s[tx][r];
        __nv_bfloat16 hi = __float2bfloat16(v);
        __nv_bfloat16 lo = __float2bfloat16(v - __bfloat162float(hi));
        g_QThi[b][n0 + r][c0 + tx] = hi;
        g_QTlo[b][n0 + r][c0 + tx] = lo;
    }
}

// ============================================================================
// K6w: reshape conv weights
// ============================================================================
__global__ void k6w_prep(const float* __restrict__ linw) {
    int idx = blockIdx.x * 256 + threadIdx.x;
    if (idx < C * 9 * C) {
        int o = idx / (9 * C);
        int k = idx % (9 * C);
        int t = k >> 7;
        int ci = k & 127;
        float w = linw[(size_t)(o * C + ci) * 9 + t];
        __nv_bfloat16 hi = __float2bfloat16(w);
        __nv_bfloat16 lo = __float2bfloat16(w - __bfloat162float(hi));
        g_W6hi[o][k] = hi;
        g_W6lo[o][k] = lo;
    }
}

// ============================================================================
// K2: heads, split across z (round-10 form)
// ============================================================================
__global__ void k2_heads(const float* __restrict__ lw1w, const float* __restrict__ lw1b,
                         const float* __restrict__ lw2w, const float* __restrict__ lw2b,
                         const float* __restrict__ bw1w, const float* __restrict__ bw1b,
                         const float* __restrict__ bw2w, const float* __restrict__ bw2b) {
    __shared__ float s_w1[MID][C];
    const int b = blockIdx.y;
    const int which = blockIdx.z;
    const int n = blockIdx.x * 256 + threadIdx.x;
    const float* w1 = which ? bw1w : lw1w;
    const float* b1 = which ? bw1b : lw1b;
    const float* w2 = which ? bw2w : lw2w;
    const float* b2 = which ? bw2b : lw2b;
    for (int e = threadIdx.x; e < MID * C; e += 256)
        s_w1[e / C][e % C] = w1[e];
    __syncthreads();

    float h[MID];
#pragma unroll
    for (int k = 0; k < MID; k++) h[k] = 0.f;
    float sq = 0.f;
#pragma unroll 4
    for (int c = 0; c < C; c++) {
        float q = g_Q[b][c][n];
        sq = fmaf(q, q, sq);
#pragma unroll
        for (int k = 0; k < MID; k++)
            h[k] = fmaf(s_w1[k][c], q, h[k]);
    }
    float v = b2[0];
#pragma unroll
    for (int k = 0; k < MID; k++) {
        float t = h[k] + b1[k];
        t = (t >= 0.f) ? t : 0.2f * t;
        v = fmaf(w2[k], t, v);
    }
    if (which) {
        g_bmap[b][n] = v;
    } else {
        g_wmap[b][n] = v;
        g_invnorm[b][n] = 1.0f / fmaxf(sqrtf(sq), 1e-4f);
    }
}

// ============================================================================
// K3 (mma.sync + cp.async staging): symmetric logits (round-13 form)
// ============================================================================
__global__ void __launch_bounds__(256, 2) k3_mma() {
    extern __shared__ char smem[];
    const uint32_t sb = smem_u32(smem);
    const int tid = threadIdx.x;
    const int wid = tid >> 5;
    const int lane = tid & 31;

    const int b = blockIdx.y;
    int rem = blockIdx.x;
    int it = 0;
    while (rem >= 32 - it) { rem -= 32 - it; it++; }
    const int jt = it + rem;
    const int n0 = it * 128;
    const int m0 = jt * 128;
    const bool diag = (it == jt);

    float* s_invn = (float*)(smem + K3_AUX);
    float* s_invm = (float*)(smem + K3_AUX + 512);
    if (tid < 128)      s_invn[tid]       = g_invnorm[b][n0 + tid];
    else                s_invm[tid - 128] = g_invnorm[b][m0 + tid - 128];

    const int wm = (wid & 1) * 64;
    const int wn = (wid >> 1) * 32;
    const uint32_t aoff = (uint32_t)((lane & 15) * (TP5 * 2) + (lane >> 4) * 16);
    const uint32_t boff = (uint32_t)((((lane >> 4) << 3) + (lane & 7)) * (TP5 * 2)
                                     + ((lane >> 3) & 1) * 16);

    const uint32_t aHiB = sb;
    const uint32_t aLoB = sb + T5B;
    const uint32_t bHiB = diag ? aHiB : (sb + 2 * T5B);
    const uint32_t bLoB = diag ? aLoB : (sb + 3 * T5B);
    const int ntiles = diag ? 2 : 4;

    float d[4][4][4];
#pragma unroll
    for (int mt = 0; mt < 4; mt++)
#pragma unroll
        for (int nt = 0; nt < 4; nt++)
#pragma unroll
            for (int q = 0; q < 4; q++) d[mt][nt][q] = 0.f;

    for (int kc = 0; kc < 2; kc++) {
        const char* srcs[4] = {
            (const char*)&g_QThi[b][n0][kc * 64], (const char*)&g_QTlo[b][n0][kc * 64],
            (const char*)&g_QThi[b][m0][kc * 64], (const char*)&g_QTlo[b][m0][kc * 64] };
        for (int i = tid; i < ntiles * 1024; i += 256) {
            int t = i >> 10;
            int row = (i >> 3) & 127;
            int q = i & 7;
            cpa16(sb + t * T5B + row * (TP5 * 2) + q * 16,
                  srcs[t] + (size_t)row * 256 + q * 16);
        }
        CPA_COMMIT();
        CPA_WAIT0();
        __syncthreads();

#pragma unroll
        for (int ks = 0; ks < 4; ks++) {
            const uint32_t kb2 = ks * 32;
            uint32_t ah[4][4], al[4][4], bh[2][4], bl[2][4];
#pragma unroll
            for (int mt = 0; mt < 4; mt++) {
                uint32_t rowb = (uint32_t)((wm + mt * 16) * (TP5 * 2)) + kb2 + aoff;
                ldsm_x4(ah[mt], aHiB + rowb);
                ldsm_x4(al[mt], aLoB + rowb);
            }
#pragma unroll
            for (int np = 0; np < 2; np++) {
                uint32_t rowb = (uint32_t)((wn + np * 16) * (TP5 * 2)) + kb2 + boff;
                ldsm_x4(bh[np], bHiB + rowb);
                ldsm_x4(bl[np], bLoB + rowb);
            }
#pragma unroll
            for (int mt = 0; mt < 4; mt++)
#pragma unroll
                for (int np = 0; np < 2; np++)
#pragma unroll
                    for (int sub = 0; sub < 2; sub++) {
                        const int nt = np * 2 + sub;
                        mma_bf16(d[mt][nt], ah[mt], &bh[np][sub * 2]);
                        mma_bf16(d[mt][nt], ah[mt], &bl[np][sub * 2]);
                        mma_bf16(d[mt][nt], al[mt], &bh[np][sub * 2]);
                    }
        }
        __syncthreads();
    }

    float* sD = (float*)smem;
    {
        const int g = lane >> 2, tg = lane & 3;
#pragma unroll
        for (int mt = 0; mt < 4; mt++) {
#pragma unroll
            for (int nt = 0; nt < 4; nt++) {
                int row0 = wm + mt * 16 + g;
                int col0 = wn + nt * 8 + 2 * tg;
                sD[row0 * 129 + col0]           = d[mt][nt][0];
                sD[row0 * 129 + col0 + 1]       = d[mt][nt][1];
                sD[(row0 + 8) * 129 + col0]     = d[mt][nt][2];
                sD[(row0 + 8) * 129 + col0 + 1] = d[mt][nt][3];
            }
        }
    }
    __syncthreads();

    float* redA = (float*)(smem + K3_AUX + 1024);
    float* redB = (float*)(smem + K3_AUX + 2048);

    {
        const int row = tid >> 1;
        const int cb = (tid & 1) * 64;
        const float invr = s_invn[row];
        float s2 = 0.f;
        float* dst = &g_L[b][n0 + row][m0];
        for (int c = cb; c < cb + 64; c += 4) {
            float d0 = sD[row * 129 + c + 0];
            float d1 = sD[row * 129 + c + 1];
            float d2 = sD[row * 129 + c + 2];
            float d3 = sD[row * 129 + c + 3];
            s2 += d0 * s_invm[c] + d1 * s_invm[c + 1] + d2 * s_invm[c + 2] + d3 * s_invm[c + 3];
            float4 o; o.x = d0 * invr; o.y = d1 * invr; o.z = d2 * invr; o.w = d3 * invr;
            *(float4*)(dst + c) = o;
        }
        redB[tid] = s2;
    }
    {
        const int col = tid >> 1;
        const int rb = (tid & 1) * 64;
        const float invc = s_invm[col];
        float s1 = 0.f;
        float* dst = &g_L[b][m0 + col][n0];
        for (int r = rb; r < rb + 64; r += 4) {
            float d0 = sD[(r + 0) * 129 + col];
            float d1 = sD[(r + 1) * 129 + col];
            float d2 = sD[(r + 2) * 129 + col];
            float d3 = sD[(r + 3) * 129 + col];
            s1 += d0 * s_invn[r] + d1 * s_invn[r + 1] + d2 * s_invn[r + 2] + d3 * s_invn[r + 3];
            if (!diag) {
                float4 o; o.x = d0 * invc; o.y = d1 * invc; o.z = d2 * invc; o.w = d3 * invc;
                *(float4*)(dst + r) = o;
            }
        }
        redA[tid] = s1;
    }
    __syncthreads();
    if (tid < 128) {
        g_psum[b][it][m0 + tid] = redA[2 * tid] + redA[2 * tid + 1];
        if (!diag)
            g_psum[b][jt][n0 + tid] = redB[2 * tid] + redB[2 * tid + 1];
    }
}

// ============================================================================
// K4b: partial online max/sum-exp (round-10 4-chain form)
// ============================================================================
__global__ void k4b_partial() {
    const int b = blockIdx.z;
    const int chunk = blockIdx.y;
    const int m = blockIdx.x * 256 + threadIdx.x;

    float ps = 0.f;
#pragma unroll
    for (int t = 0; t < 32; t++) ps += g_psum[b][t][m];
    const float mean = ps * (1.0f / N);
    const float off = g_bmap[b][m] - mean * g_wmap[b][m];
    if (chunk == 0) g_off[b][m] = off;

    const int nbase = chunk * 256;
    float mx0 = -1e30f, mx1 = -1e30f, mx2 = -1e30f, mx3 = -1e30f;
    float s0 = 0.f, s1 = 0.f, s2 = 0.f, s3 = 0.f;

#define CHAIN(MX, S, L) { float sp = fmaxf((L) + off, 0.f); float z = (L) * sp; \
    if (z <= MX) { S += __expf(z - MX); } else { S = S * __expf(MX - z) + 1.f; MX = z; } }

#pragma unroll 2
    for (int r = 0; r < 256; r += 4) {
        float l0 = g_L[b][nbase + r + 0][m];
        float l1 = g_L[b][nbase + r + 1][m];
        float l2 = g_L[b][nbase + r + 2][m];
        float l3 = g_L[b][nbase + r + 3][m];
        CHAIN(mx0, s0, l0);
        CHAIN(mx1, s1, l1);
        CHAIN(mx2, s2, l2);
        CHAIN(mx3, s3, l3);
    }
#undef CHAIN
    float M = fmaxf(fmaxf(mx0, mx1), fmaxf(mx2, mx3));
    float S = s0 * __expf(mx0 - M) + s1 * __expf(mx1 - M)
            + s2 * __expf(mx2 - M) + s3 * __expf(mx3 - M);
    g_pmx[b][chunk][m] = M;
    g_psm[b][chunk][m] = S;
}

// ============================================================================
// K5 (mma.sync + cp.async, single-sync pipeline, B double-buffered)
// schedule: MMA(i) | wait data(i+1) | sync | transform(i+1) | issue(i+2)
// ============================================================================
__global__ void __launch_bounds__(256, 1) k5_mma() {
    extern __shared__ char smem[];
    const uint32_t sb = smem_u32(smem);
    const int tid = threadIdx.x;
    const int wid = tid >> 5;
    const int lane = tid & 31;
    const int b = blockIdx.y;
    const int m0 = blockIdx.x * 128;

    float* p_off = (float*)(smem + K5_AUX);
    float* p_mx  = (float*)(smem + K5_AUX + 512);
    float* p_si  = (float*)(smem + K5_AUX + 1024);
    if (tid < 128) {
        int m = m0 + tid;
        p_off[tid] = g_off[b][m];
        float M = g_pmx[b][0][m];
        float S = g_psm[b][0][m];
#pragma unroll
        for (int t = 1; t < 16; t++) {
            float m2 = g_pmx[b][t][m], s2 = g_psm[b][t][m];
            float Mn = fmaxf(M, m2);
            S = S * __expf(M - Mn) + s2 * __expf(m2 - Mn);
            M = Mn;
        }
        p_mx[tid] = M;
        p_si[tid] = 1.0f / S;
    }

    const int wm = (wid & 1) * 64;
    const int wn = (wid >> 1) * 32;
    const uint32_t aoff = (uint32_t)((lane & 15) * (TP5 * 2) + (lane >> 4) * 16);
    const uint32_t boff = (uint32_t)((((lane >> 4) << 3) + (lane & 7)) * (TP5 * 2)
                                     + ((lane >> 3) & 1) * 16);

    const int mm0 = (tid & 31) * 4;
    const int kk0 = (tid >> 5) * 8;

    float d[4][4][4];
#pragma unroll
    for (int mt = 0; mt < 4; mt++)
#pragma unroll
        for (int nt = 0; nt < 4; nt++)
#pragma unroll
            for (int q = 0; q < 4; q++) d[mt][nt][q] = 0.f;

#define K5_ISSUE(BUFI, NBASE) do {                                               \
        uint32_t abase = sb + (BUFI) * (2 * T5B);                                \
        for (int i = tid; i < 1024; i += 256) {                                  \
            int r = i >> 3, q = i & 7;                                           \
            cpa16(abase + r * (TP5 * 2) + q * 16,                                \
                  (const char*)&g_Vhi[b][r][NBASE] + q * 16);                    \
            cpa16(abase + T5B + r * (TP5 * 2) + q * 16,                          \
                  (const char*)&g_Vlo[b][r][NBASE] + q * 16);                    \
        }                                                                        \
        uint32_t lbase = sb + K5_LR + (BUFI) * 32768;                            \
        for (int i = tid; i < 2048; i += 256) {                                  \
            int kk = i >> 5, q = i & 31;                                         \
            cpa16(lbase + kk * 512 + q * 16,                                     \
                  (const char*)&g_L[b][NBASE + kk][m0] + q * 16);                \
        }                                                                        \
    } while (0)

// transform chunk data (already in smem buffer BUFI) -> B[BUFI]
#define K5_TRANSFORM(BUFI) do {                                                  \
        const float* Lr = (const float*)(smem + K5_LR + (BUFI) * 32768);         \
        uint32_t whi[4][4], wlo[4][4];                                           \
        _Pragma("unroll")                                                        \
        for (int j = 0; j < 4; j++)                                              \
            _Pragma("unroll")                                                    \
            for (int p = 0; p < 4; p++) { whi[j][p] = 0u; wlo[j][p] = 0u; }      \
        _Pragma("unroll")                                                        \
        for (int kk = 0; kk < 8; kk++) {                                         \
            float4 l4 = *(const float4*)(Lr + (kk0 + kk) * 128 + mm0);           \
            float ls[4] = {l4.x, l4.y, l4.z, l4.w};                              \
            _Pragma("unroll")                                                    \
            for (int j = 0; j < 4; j++) {                                        \
                int m = mm0 + j;                                                 \
                float l = ls[j];                                                 \
                float sp = fmaxf(l + p_off[m], 0.f);                             \
                float a;                                                         \
                if (sp > 0.f)                                                    \
                    a = fmaxf(__expf(l * sp - p_mx[m]) * p_si[m], 1e-8f);        \
                else                                                             \
                    a = 1e-8f;                                                   \
                __nv_bfloat16 h = __float2bfloat16(a);                           \
                __nv_bfloat16 lo = __float2bfloat16(a - __bfloat162float(h));    \
                uint32_t sh = (uint32_t)(kk & 1) * 16;                           \
                whi[j][kk >> 1] |= (uint32_t)__bfloat16_as_ushort(h) << sh;      \
                wlo[j][kk >> 1] |= (uint32_t)__bfloat16_as_ushort(lo) << sh;     \
            }                                                                    \
        }                                                                        \
        char* bbase = smem + K5_B + (BUFI) * (2 * T5B);                          \
        _Pragma("unroll")                                                        \
        for (int j = 0; j < 4; j++) {                                            \
            uint4 vh; vh.x = whi[j][0]; vh.y = whi[j][1]; vh.z = whi[j][2]; vh.w = whi[j][3]; \
            uint4 vl; vl.x = wlo[j][0]; vl.y = wlo[j][1]; vl.z = wlo[j][2]; vl.w = wlo[j][3]; \
            *(uint4*)(bbase + (mm0 + j) * (TP5 * 2) + kk0 * 2) = vh;             \
            *(uint4*)(bbase + T5B + (mm0 + j) * (TP5 * 2) + kk0 * 2) = vl;       \
        }                                                                        \
    } while (0)

    // prologue: stage chunk 0, transform it, issue chunk 1
    K5_ISSUE(0, 0);
    CPA_COMMIT();
    CPA_WAIT0();
    __syncthreads();
    K5_TRANSFORM(0);
    K5_ISSUE(1, 64);
    CPA_COMMIT();
    __syncthreads();   // B[0] ready for MMA(0)

    for (int ic = 0; ic < 64; ic++) {
        const int cur = ic & 1;
        const uint32_t abase = sb + cur * (2 * T5B);
        const uint32_t bbase = sb + K5_B + cur * (2 * T5B);
#pragma unroll
        for (int ks = 0; ks < 4; ks++) {
            const uint32_t kb2 = ks * 32;
            uint32_t ah[4][4], al[4][4], bh[2][4], bl[2][4];
#pragma unroll
            for (int mt = 0; mt < 4; mt++) {
                uint32_t rowb = (uint32_t)((wm + mt * 16) * (TP5 * 2)) + kb2 + aoff;
                ldsm_x4(ah[mt], abase + rowb);
                ldsm_x4(al[mt], abase + T5B + rowb);
            }
#pragma unroll
            for (int np = 0; np < 2; np++) {
                uint32_t rowb = (uint32_t)((wn + np * 16) * (TP5 * 2)) + kb2 + boff;
                ldsm_x4(bh[np], bbase + rowb);
                ldsm_x4(bl[np], bbase + T5B + rowb);
            }
#pragma unroll
            for (int mt = 0; mt < 4; mt++)
#pragma unroll
                for (int np = 0; np < 2; np++)
#pragma unroll
                    for (int sub = 0; sub < 2; sub++) {
                        const int nt = np * 2 + sub;
                        mma_bf16(d[mt][nt], ah[mt], &bh[np][sub * 2]);
                        mma_bf16(d[mt][nt], ah[mt], &bl[np][sub * 2]);
                        mma_bf16(d[mt][nt], al[mt], &bh[np][sub * 2]);
                    }
        }

        if (ic + 1 < 64) {
            CPA_WAIT0();        // data for chunk ic+1 fully arrived
            __syncthreads();    // all threads see it; MMA(ic) done (B buffers alternate)
            K5_TRANSFORM((ic + 1) & 1);
            if (ic + 2 < 64) {
                K5_ISSUE(ic & 1, (ic + 2) * 64);   // reuse buffer of chunk ic
                CPA_COMMIT();
            }
            __syncthreads();    // B[(ic+1)&1] ready
        }
    }
#undef K5_ISSUE
#undef K5_TRANSFORM

    __syncthreads();
    float* sD = (float*)smem;
    {
        const int g = lane >> 2, tg = lane & 3;
#pragma unroll
        for (int mt = 0; mt < 4; mt++) {
#pragma unroll
            for (int nt = 0; nt < 4; nt++) {
                int row0 = wm + mt * 16 + g;
                int col0 = wn + nt * 8 + 2 * tg;
                sD[row0 * 129 + col0]           = d[mt][nt][0];
                sD[row0 * 129 + col0 + 1]       = d[mt][nt][1];
                sD[(row0 + 8) * 129 + col0]     = d[mt][nt][2];
                sD[(row0 + 8) * 129 + col0 + 1] = d[mt][nt][3];
            }
        }
    }
    __syncthreads();
    {
        const int m = tid >> 1;
        const int cb = (tid & 1) * 64;
        uint32_t hibuf[32], lobuf[32];
#pragma unroll 8
        for (int u = 0; u < 32; u++) {
            float v0 = sD[(cb + 2 * u) * 129 + m];
            float v1 = sD[(cb + 2 * u + 1) * 129 + m];
            __nv_bfloat16 h0 = __float2bfloat16(v0);
            __nv_bfloat16 h1 = __float2bfloat16(v1);
            __nv_bfloat16 l0 = __float2bfloat16(v0 - __bfloat162float(h0));
            __nv_bfloat16 l1 = __float2bfloat16(v1 - __bfloat162float(h1));
            hibuf[u] = (uint32_t)__bfloat16_as_ushort(h0) | ((uint32_t)__bfloat16_as_ushort(h1) << 16);
            lobuf[u] = (uint32_t)__bfloat16_as_ushort(l0) | ((uint32_t)__bfloat16_as_ushort(l1) << 16);
        }
#pragma unroll
        for (int q = 0; q < 8; q++) {
            *(uint4*)&g_YTh[b][m0 + m][cb + q * 8] = *(uint4*)&hibuf[q * 4];
            *(uint4*)&g_YTl[b][m0 + m][cb + q * 8] = *(uint4*)&lobuf[q * 4];
        }
    }
}

// ============================================================================
// K6 (mma.sync + cp.async double buffer): conv3x3 implicit GEMM  [round-10]
// ============================================================================
__global__ void __launch_bounds__(256, 1) k6_mma(const float* __restrict__ linb,
                                                 const float* __restrict__ x,
                                                 float* __restrict__ out) {
    extern __shared__ char smem[];
    const uint32_t sb = smem_u32(smem);
    const int tid = threadIdx.x;
    const int wid = tid >> 5;
    const int lane = tid & 31;
    const int b = blockIdx.y;
    const int p0 = blockIdx.x * 128;

    const int wm = (wid & 1) * 64;
    const int wn = (wid >> 1) * 32;
    const uint32_t aoff = (uint32_t)((lane & 15) * (TP5 * 2) + (lane >> 4) * 16);
    const uint32_t boff = (uint32_t)((((lane >> 4) << 3) + (lane & 7)) * (TP5 * 2)
                                     + ((lane >> 3) & 1) * 16);

    float d[4][4][4];
#pragma unroll
    for (int mt = 0; mt < 4; mt++)
#pragma unroll
        for (int nt = 0; nt < 4; nt++)
#pragma unroll
            for (int q = 0; q < 4; q++) d[mt][nt][q] = 0.f;

#define K6_ISSUE(BUFI, T, CB) do {                                               \
        uint32_t base = sb + (BUFI) * (4 * T5B);                                 \
        for (int i = tid; i < 1024; i += 256) {                                  \
            int r = i >> 3, q = i & 7;                                           \
            cpa16(base + r * (TP5 * 2) + q * 16,                                 \
                  (const char*)&g_W6hi[r][(T) * 128 + (CB)] + q * 16);           \
            cpa16(base + T5B + r * (TP5 * 2) + q * 16,                           \
                  (const char*)&g_W6lo[r][(T) * 128 + (CB)] + q * 16);           \
        }                                                                        \
        {                                                                        \
            int dh = (T) / 3 - 1, dw = (T) % 3 - 1;                              \
            for (int i = tid; i < 1024; i += 256) {                              \
                int r = i >> 3, q = i & 7;                                       \
                int p = p0 + r;                                                  \
                int h = (p >> 6) + dh, w = (p & 63) + dw;                        \
                uint32_t dsth = base + 2 * T5B + r * (TP5 * 2) + q * 16;         \
                uint32_t dstl = base + 3 * T5B + r * (TP5 * 2) + q * 16;         \
                if (h >= 0 && h < HW && w >= 0 && w < HW) {                      \
                    int src = (h << 6) + w;                                      \
                    cpa16(dsth, (const char*)&g_YTh[b][src][CB] + q * 16);       \
                    cpa16(dstl, (const char*)&g_YTl[b][src][CB] + q * 16);       \
                } else {                                                         \
                    uint4 z = make_uint4(0u, 0u, 0u, 0u);                        \
                    *(uint4*)(smem + (BUFI) * (4 * T5B) + 2 * T5B + r * (TP5 * 2) + q * 16) = z; \
                    *(uint4*)(smem + (BUFI) * (4 * T5B) + 3 * T5B + r * (TP5 * 2) + q * 16) = z; \
                }                                                                \
            }                                                                    \
        }                                                                        \
    } while (0)

    K6_ISSUE(0, 0, 0);
    CPA_COMMIT();

    for (int ic = 0; ic < 18; ic++) {
        const int cur = ic & 1;
        if (ic + 1 < 18) {
            K6_ISSUE(cur ^ 1, (ic + 1) >> 1, ((ic + 1) & 1) * 64);
            CPA_COMMIT();
            CPA_WAIT1();
        } else {
            CPA_WAIT0();
        }
        __syncthreads();

        const uint32_t base = sb + cur * (4 * T5B);
#pragma unroll
        for (int ks = 0; ks < 4; ks++) {
            const uint32_t kb2 = ks * 32;
            uint32_t ah[4][4], al[4][4], bh[2][4], bl[2][4];
#pragma unroll
            for (int mt = 0; mt < 4; mt++) {
                uint32_t rowb = (uint32_t)((wm + mt * 16) * (TP5 * 2)) + kb2 + aoff;
                ldsm_x4(ah[mt], base + rowb);
                ldsm_x4(al[mt], base + T5B + rowb);
            }
#pragma unroll
            for (int np = 0; np < 2; np++) {
                uint32_t rowb = (uint32_t)((wn + np * 16) * (TP5 * 2)) + kb2 + boff;
                ldsm_x4(bh[np], base + 2 * T5B + rowb);
                ldsm_x4(bl[np], base + 3 * T5B + rowb);
            }
#pragma unroll
            for (int mt = 0; mt < 4; mt++)
#pragma unroll
                for (int np = 0; np < 2; np++)
#pragma unroll
                    for (int sub = 0; sub < 2; sub++) {
                        const int nt = np * 2 + sub;
                        mma_bf16(d[mt][nt], ah[mt], &bh[np][sub * 2]);
                        mma_bf16(d[mt][nt], ah[mt], &bl[np][sub * 2]);
                        mma_bf16(d[mt][nt], al[mt], &bh[np][sub * 2]);
                    }
        }
        __syncthreads();
    }
#undef K6_ISSUE

    {
        const int g = lane >> 2, tg = lane & 3;
#pragma unroll
        for (int mt = 0; mt < 4; mt++) {
            int o0 = wm + mt * 16 + g;
            float b0 = linb[o0];
            float b1 = linb[o0 + 8];
#pragma unroll
            for (int nt = 0; nt < 4; nt++) {
                int col0 = p0 + wn + nt * 8 + 2 * tg;
                size_t base0 = ((size_t)b * C + o0) * N + col0;
                size_t base1 = ((size_t)b * C + o0 + 8) * N + col0;
                float2 xr0 = *(const float2*)(x + base0);
                float2 xr1 = *(const float2*)(x + base1);
                float v00 = d[mt][nt][0] + b0;
                float v01 = d[mt][nt][1] + b0;
                float v10 = d[mt][nt][2] + b1;
                float v11 = d[mt][nt][3] + b1;
                v00 = (v00 >= 0.f) ? v00 : 0.2f * v00;
                v01 = (v01 >= 0.f) ? v01 : 0.2f * v01;
                v10 = (v10 >= 0.f) ? v10 : 0.2f * v10;
                v11 = (v11 >= 0.f) ? v11 : 0.2f * v11;
                float2 o0v; o0v.x = v00 + xr0.x; o0v.y = v01 + xr0.y;
                float2 o1v; o1v.x = v10 + xr1.x; o1v.y = v11 + xr1.y;
                *(float2*)(out + base0) = o0v;
                *(float2*)(out + base1) = o1v;
            }
        }
    }
}

// ============================================================================
extern "C" void kernel_launch(void* const* d_in, const int* in_sizes, int n_in,
                              void* d_out, int out_size) {
    const float* x     = (const float*)d_in[0];
    const float* q_w   = (const float*)d_in[1];
    const float* q_b   = (const float*)d_in[2];
    const float* v_w   = (const float*)d_in[3];
    const float* v_b   = (const float*)d_in[4];
    const float* lw1_w = (const float*)d_in[5];
    const float* lw1_b = (const float*)d_in[6];
    const float* lw2_w = (const float*)d_in[7];
    const float* lw2_b = (const float*)d_in[8];
    const float* bw1_w = (const float*)d_in[9];
    const float* bw1_b = (const float*)d_in[10];
    const float* bw2_w = (const float*)d_in[11];
    const float* bw2_b = (const float*)d_in[12];
    const float* lin_w = (const float*)d_in[13];
    const float* lin_b = (const float*)d_in[14];
    float* out = (float*)d_out;

    cudaFuncSetAttribute(k3_mma, cudaFuncAttributeMaxDynamicSharedMemorySize, K3_SMEM_BYTES);
    cudaFuncSetAttribute(k5_mma, cudaFuncAttributeMaxDynamicSharedMemorySize, K5_SMEM_BYTES);
    cudaFuncSetAttribute(k6_mma, cudaFuncAttributeMaxDynamicSharedMemorySize, K6_SMEM_BYTES);

    k6w_prep<<<(C * 9 * C + 255) / 256, 256>>>(lin_w);
    k1_qv<<<dim3(N / 128, BATCH, 2), 256>>>(x, q_w, q_b, v_w, v_b);
    k1t_transpose<<<dim3(N / 32, C / 32, BATCH), 256>>>();
    k2_heads<<<dim3(N / 256, BATCH, 2), 256>>>(lw1_w, lw1_b, lw2_w, lw2_b,
                                               bw1_w, bw1_b, bw2_w, bw2_b);
    k3_mma<<<dim3(528, BATCH), 256, K3_SMEM_BYTES>>>();
    k4b_partial<<<dim3(16, 16, BATCH), 256>>>();
    k5_mma<<<dim3(N / 128, BATCH), 256, K5_SMEM_BYTES>>>();
    k6_mma<<<dim3(N / 128, BATCH), 256, K6_SMEM_BYTES>>>(lin_b, x, out);
}

// round 15
// speedup vs baseline: 1.1883x; 1.1193x over previous
#include <cuda_runtime.h>
#include <cuda_bf16.h>
#include <cstdint>
#include <math.h>

#define BATCH 4
#define C 128
#define MID 32
#define HW 64
#define N 4096   // HW*HW

// ---------------- static device scratch ----------------
__device__ float g_Q[BATCH][C][N];
__device__ __nv_bfloat16 g_QThi[BATCH][N][C];
__device__ __nv_bfloat16 g_QTlo[BATCH][N][C];
__device__ __nv_bfloat16 g_Vhi[BATCH][C][N];
__device__ __nv_bfloat16 g_Vlo[BATCH][C][N];
__device__ __nv_bfloat16 g_W6hi[C][9 * C];
__device__ __nv_bfloat16 g_W6lo[C][9 * C];
__device__ __nv_bfloat16 g_YTh[BATCH][N][C];
__device__ __nv_bfloat16 g_YTl[BATCH][N][C];
__device__ float g_invnorm[BATCH][N];
__device__ float g_wmap[BATCH][N];
__device__ float g_bmap[BATCH][N];
__device__ float g_off[BATCH][N];
__device__ float g_L[BATCH][N][N];
__device__ float g_psum[BATCH][32][N];
__device__ float g_pmx[BATCH][16][N];
__device__ float g_psm[BATCH][16][N];

// ---------------- helpers ----------------
__device__ __forceinline__ uint32_t smem_u32(const void* p) {
    uint32_t a;
    asm("{ .reg .u64 t; cvta.to.shared.u64 t, %1; cvt.u32.u64 %0, t; }" : "=r"(a) : "l"(p));
    return a;
}
__device__ __forceinline__ void ldsm_x4(uint32_t* r, uint32_t addr) {
    asm volatile("ldmatrix.sync.aligned.m8n8.x4.shared.b16 {%0,%1,%2,%3}, [%4];"
                 : "=r"(r[0]), "=r"(r[1]), "=r"(r[2]), "=r"(r[3]) : "r"(addr));
}
__device__ __forceinline__ void mma_bf16(float* d, const uint32_t* a, const uint32_t* b) {
    asm volatile(
        "mma.sync.aligned.m16n8k16.row.col.f32.bf16.bf16.f32 "
        "{%0,%1,%2,%3}, {%4,%5,%6,%7}, {%8,%9}, {%0,%1,%2,%3};"
        : "+f"(d[0]), "+f"(d[1]), "+f"(d[2]), "+f"(d[3])
        : "r"(a[0]), "r"(a[1]), "r"(a[2]), "r"(a[3]), "r"(b[0]), "r"(b[1]));
}
__device__ __forceinline__ void cpa16(uint32_t dst, const void* src) {
    asm volatile("cp.async.cg.shared.global [%0], [%1], 16;" :: "r"(dst), "l"(src));
}
#define CPA_COMMIT() asm volatile("cp.async.commit_group;" ::: "memory")
#define CPA_WAIT1() asm volatile("cp.async.wait_group 1;" ::: "memory")
#define CPA_WAIT0() asm volatile("cp.async.wait_group 0;" ::: "memory")

#define TP5 72
#define T5B (128 * TP5 * 2)                // 18432

#define K3_AUX (4 * T5B)                   // 73728
#define K3_SMEM_BYTES (K3_AUX + 3072)      // 76800 -> 2 CTAs/SM

#define K5_LR (4 * T5B)                    // 73728
#define K5_B  (K5_LR + 65536)              // 139264  (two B hi/lo pairs follow)
#define K5_AUX (K5_B + 4 * T5B)            // 212992
#define K5_SMEM_BYTES (K5_AUX + 1536)      // 214528

#define K6_SMEM_BYTES (8 * T5B)            // 147456

// ============================================================================
// K1: Q/V 1x1 convs (V emitted only as bf16 hi/lo)
// ============================================================================
__global__ void k1_qv(const float* __restrict__ x,
                      const float* __restrict__ qw, const float* __restrict__ qb,
                      const float* __restrict__ vw, const float* __restrict__ vb) {
    const int b = blockIdx.y;
    const int which = blockIdx.z;
    const float* W = which ? vw : qw;
    const float* bias = which ? vb : qb;
    const int n0 = blockIdx.x * 128;
    const float* xb = x + (size_t)b * C * N;

    __shared__ float As[16][128];
    __shared__ float Bs[16][128];
    const int tid = threadIdx.x;
    const int tx = tid & 15, ty = tid >> 4;

    float acc[8][8];
#pragma unroll
    for (int i = 0; i < 8; i++)
#pragma unroll
        for (int j = 0; j < 8; j++) acc[i][j] = 0.f;

    for (int k0 = 0; k0 < 128; k0 += 16) {
        {
            int o = tid >> 1;
            int kb = (tid & 1) * 8;
            float4 a0 = *(const float4*)(W + o * 128 + k0 + kb);
            float4 a1 = *(const float4*)(W + o * 128 + k0 + kb + 4);
            As[kb + 0][o] = a0.x; As[kb + 1][o] = a0.y; As[kb + 2][o] = a0.z; As[kb + 3][o] = a0.w;
            As[kb + 4][o] = a1.x; As[kb + 5][o] = a1.y; As[kb + 6][o] = a1.z; As[kb + 7][o] = a1.w;
        }
        {
            int kk = tid >> 4;
            int nn = (tid & 15) * 8;
            *(float4*)&Bs[kk][nn]     = *(const float4*)(xb + (size_t)(k0 + kk) * N + n0 + nn);
            *(float4*)&Bs[kk][nn + 4] = *(const float4*)(xb + (size_t)(k0 + kk) * N + n0 + nn + 4);
        }
        __syncthreads();
#pragma unroll
        for (int kk = 0; kk < 16; kk++) {
            float ra[8], rb[8];
            *(float4*)&ra[0] = *(const float4*)&As[kk][ty * 8];
            *(float4*)&ra[4] = *(const float4*)&As[kk][ty * 8 + 4];
            *(float4*)&rb[0] = *(const float4*)&Bs[kk][tx * 8];
            *(float4*)&rb[4] = *(const float4*)&Bs[kk][tx * 8 + 4];
#pragma unroll
            for (int i = 0; i < 8; i++)
#pragma unroll
                for (int j = 0; j < 8; j++)
                    acc[i][j] = fmaf(ra[i], rb[j], acc[i][j]);
        }
        __syncthreads();
    }
#pragma unroll
    for (int i = 0; i < 8; i++) {
        int o = ty * 8 + i;
        float bo = bias[o];
        float r[8];
#pragma unroll
        for (int j = 0; j < 8; j++) r[j] = acc[i][j] + bo;
        if (!which) {
            *(float4*)(&g_Q[b][o][n0 + tx * 8])     = *(float4*)&r[0];
            *(float4*)(&g_Q[b][o][n0 + tx * 8 + 4]) = *(float4*)&r[4];
        } else {
            uint32_t whi[4], wlo[4];
#pragma unroll
            for (int p = 0; p < 4; p++) {
                __nv_bfloat16 h0 = __float2bfloat16(r[2 * p]);
                __nv_bfloat16 h1 = __float2bfloat16(r[2 * p + 1]);
                __nv_bfloat16 l0 = __float2bfloat16(r[2 * p] - __bfloat162float(h0));
                __nv_bfloat16 l1 = __float2bfloat16(r[2 * p + 1] - __bfloat162float(h1));
                whi[p] = (uint32_t)__bfloat16_as_ushort(h0) | ((uint32_t)__bfloat16_as_ushort(h1) << 16);
                wlo[p] = (uint32_t)__bfloat16_as_ushort(l0) | ((uint32_t)__bfloat16_as_ushort(l1) << 16);
            }
            uint4 vh; vh.x = whi[0]; vh.y = whi[1]; vh.z = whi[2]; vh.w = whi[3];
            uint4 vl; vl.x = wlo[0]; vl.y = wlo[1]; vl.z = wlo[2]; vl.w = wlo[3];
            *(uint4*)&g_Vhi[b][o][n0 + tx * 8] = vh;
            *(uint4*)&g_Vlo[b][o][n0 + tx * 8] = vl;
        }
    }
}

// ============================================================================
// K1t: transpose Q -> QT bf16 hi/lo
// ============================================================================
__global__ void k1t_transpose() {
    __shared__ float s[32][33];
    const int b = blockIdx.z;
    const int c0 = blockIdx.y * 32;
    const int n0 = blockIdx.x * 32;
    const int tid = threadIdx.x;
    const int tx = tid & 31, ty = tid >> 5;

#pragma unroll
    for (int p = 0; p < 4; p++)
        s[ty + 8 * p][tx] = g_Q[b][c0 + ty + 8 * p][n0 + tx];
    __syncthreads();
#pragma unroll
    for (int p = 0; p < 4; p++) {
        int r = ty + 8 * p;
        float v = s[tx][r];
        __nv_bfloat16 hi = __float2bfloat16(v);
        __nv_bfloat16 lo = __float2bfloat16(v - __bfloat162float(hi));
        g_QThi[b][n0 + r][c0 + tx] = hi;
        g_QTlo[b][n0 + r][c0 + tx] = lo;
    }
}

// ============================================================================
// K6w: reshape conv weights
// ============================================================================
__global__ void k6w_prep(const float* __restrict__ linw) {
    int idx = blockIdx.x * 256 + threadIdx.x;
    if (idx < C * 9 * C) {
        int o = idx / (9 * C);
        int k = idx % (9 * C);
        int t = k >> 7;
        int ci = k & 127;
        float w = linw[(size_t)(o * C + ci) * 9 + t];
        __nv_bfloat16 hi = __float2bfloat16(w);
        __nv_bfloat16 lo = __float2bfloat16(w - __bfloat162float(hi));
        g_W6hi[o][k] = hi;
        g_W6lo[o][k] = lo;
    }
}

// ============================================================================
// K2: heads, split across z (round-10 form)
// ============================================================================
__global__ void k2_heads(const float* __restrict__ lw1w, const float* __restrict__ lw1b,
                         const float* __restrict__ lw2w, const float* __restrict__ lw2b,
                         const float* __restrict__ bw1w, const float* __restrict__ bw1b,
                         const float* __restrict__ bw2w, const float* __restrict__ bw2b) {
    __shared__ float s_w1[MID][C];
    const int b = blockIdx.y;
    const int which = blockIdx.z;
    const int n = blockIdx.x * 256 + threadIdx.x;
    const float* w1 = which ? bw1w : lw1w;
    const float* b1 = which ? bw1b : lw1b;
    const float* w2 = which ? bw2w : lw2w;
    const float* b2 = which ? bw2b : lw2b;
    for (int e = threadIdx.x; e < MID * C; e += 256)
        s_w1[e / C][e % C] = w1[e];
    __syncthreads();

    float h[MID];
#pragma unroll
    for (int k = 0; k < MID; k++) h[k] = 0.f;
    float sq = 0.f;
#pragma unroll 4
    for (int c = 0; c < C; c++) {
        float q = g_Q[b][c][n];
        sq = fmaf(q, q, sq);
#pragma unroll
        for (int k = 0; k < MID; k++)
            h[k] = fmaf(s_w1[k][c], q, h[k]);
    }
    float v = b2[0];
#pragma unroll
    for (int k = 0; k < MID; k++) {
        float t = h[k] + b1[k];
        t = (t >= 0.f) ? t : 0.2f * t;
        v = fmaf(w2[k], t, v);
    }
    if (which) {
        g_bmap[b][n] = v;
    } else {
        g_wmap[b][n] = v;
        g_invnorm[b][n] = 1.0f / fmaxf(sqrtf(sq), 1e-4f);
    }
}

// ============================================================================
// K3 (mma.sync + cp.async staging): symmetric logits (round-13 form)
// ============================================================================
__global__ void __launch_bounds__(256, 2) k3_mma() {
    extern __shared__ char smem[];
    const uint32_t sb = smem_u32(smem);
    const int tid = threadIdx.x;
    const int wid = tid >> 5;
    const int lane = tid & 31;

    const int b = blockIdx.y;
    int rem = blockIdx.x;
    int it = 0;
    while (rem >= 32 - it) { rem -= 32 - it; it++; }
    const int jt = it + rem;
    const int n0 = it * 128;
    const int m0 = jt * 128;
    const bool diag = (it == jt);

    float* s_invn = (float*)(smem + K3_AUX);
    float* s_invm = (float*)(smem + K3_AUX + 512);
    if (tid < 128)      s_invn[tid]       = g_invnorm[b][n0 + tid];
    else                s_invm[tid - 128] = g_invnorm[b][m0 + tid - 128];

    const int wm = (wid & 1) * 64;
    const int wn = (wid >> 1) * 32;
    const uint32_t aoff = (uint32_t)((lane & 15) * (TP5 * 2) + (lane >> 4) * 16);
    const uint32_t boff = (uint32_t)((((lane >> 4) << 3) + (lane & 7)) * (TP5 * 2)
                                     + ((lane >> 3) & 1) * 16);

    const uint32_t aHiB = sb;
    const uint32_t aLoB = sb + T5B;
    const uint32_t bHiB = diag ? aHiB : (sb + 2 * T5B);
    const uint32_t bLoB = diag ? aLoB : (sb + 3 * T5B);
    const int ntiles = diag ? 2 : 4;

    float d[4][4][4];
#pragma unroll
    for (int mt = 0; mt < 4; mt++)
#pragma unroll
        for (int nt = 0; nt < 4; nt++)
#pragma unroll
            for (int q = 0; q < 4; q++) d[mt][nt][q] = 0.f;

    for (int kc = 0; kc < 2; kc++) {
        const char* srcs[4] = {
            (const char*)&g_QThi[b][n0][kc * 64], (const char*)&g_QTlo[b][n0][kc * 64],
            (const char*)&g_QThi[b][m0][kc * 64], (const char*)&g_QTlo[b][m0][kc * 64] };
        for (int i = tid; i < ntiles * 1024; i += 256) {
            int t = i >> 10;
            int row = (i >> 3) & 127;
            int q = i & 7;
            cpa16(sb + t * T5B + row * (TP5 * 2) + q * 16,
                  srcs[t] + (size_t)row * 256 + q * 16);
        }
        CPA_COMMIT();
        CPA_WAIT0();
        __syncthreads();

#pragma unroll
        for (int ks = 0; ks < 4; ks++) {
            const uint32_t kb2 = ks * 32;
            uint32_t ah[4][4], al[4][4], bh[2][4], bl[2][4];
#pragma unroll
            for (int mt = 0; mt < 4; mt++) {
                uint32_t rowb = (uint32_t)((wm + mt * 16) * (TP5 * 2)) + kb2 + aoff;
                ldsm_x4(ah[mt], aHiB + rowb);
                ldsm_x4(al[mt], aLoB + rowb);
            }
#pragma unroll
            for (int np = 0; np < 2; np++) {
                uint32_t rowb = (uint32_t)((wn + np * 16) * (TP5 * 2)) + kb2 + boff;
                ldsm_x4(bh[np], bHiB + rowb);
                ldsm_x4(bl[np], bLoB + rowb);
            }
#pragma unroll
            for (int mt = 0; mt < 4; mt++)
#pragma unroll
                for (int np = 0; np < 2; np++)
#pragma unroll
                    for (int sub = 0; sub < 2; sub++) {
                        const int nt = np * 2 + sub;
                        mma_bf16(d[mt][nt], ah[mt], &bh[np][sub * 2]);
                        mma_bf16(d[mt][nt], ah[mt], &bl[np][sub * 2]);
                        mma_bf16(d[mt][nt], al[mt], &bh[np][sub * 2]);
                    }
        }
        __syncthreads();
    }

    float* sD = (float*)smem;
    {
        const int g = lane >> 2, tg = lane & 3;
#pragma unroll
        for (int mt = 0; mt < 4; mt++) {
#pragma unroll
            for (int nt = 0; nt < 4; nt++) {
                int row0 = wm + mt * 16 + g;
                int col0 = wn + nt * 8 + 2 * tg;
                sD[row0 * 129 + col0]           = d[mt][nt][0];
                sD[row0 * 129 + col0 + 1]       = d[mt][nt][1];
                sD[(row0 + 8) * 129 + col0]     = d[mt][nt][2];
                sD[(row0 + 8) * 129 + col0 + 1] = d[mt][nt][3];
            }
        }
    }
    __syncthreads();

    float* redA = (float*)(smem + K3_AUX + 1024);
    float* redB = (float*)(smem + K3_AUX + 2048);

    {
        const int row = tid >> 1;
        const int cb = (tid & 1) * 64;
        const float invr = s_invn[row];
        float s2 = 0.f;
        float* dst = &g_L[b][n0 + row][m0];
        for (int c = cb; c < cb + 64; c += 4) {
            float d0 = sD[row * 129 + c + 0];
            float d1 = sD[row * 129 + c + 1];
            float d2 = sD[row * 129 + c + 2];
            float d3 = sD[row * 129 + c + 3];
            s2 += d0 * s_invm[c] + d1 * s_invm[c + 1] + d2 * s_invm[c + 2] + d3 * s_invm[c + 3];
            float4 o; o.x = d0 * invr; o.y = d1 * invr; o.z = d2 * invr; o.w = d3 * invr;
            *(float4*)(dst + c) = o;
        }
        redB[tid] = s2;
    }
    {
        const int col = tid >> 1;
        const int rb = (tid & 1) * 64;
        const float invc = s_invm[col];
        float s1 = 0.f;
        float* dst = &g_L[b][m0 + col][n0];
        for (int r = rb; r < rb + 64; r += 4) {
            float d0 = sD[(r + 0) * 129 + col];
            float d1 = sD[(r + 1) * 129 + col];
            float d2 = sD[(r + 2) * 129 + col];
            float d3 = sD[(r + 3) * 129 + col];
            s1 += d0 * s_invn[r] + d1 * s_invn[r + 1] + d2 * s_invn[r + 2] + d3 * s_invn[r + 3];
            if (!diag) {
                float4 o; o.x = d0 * invc; o.y = d1 * invc; o.z = d2 * invc; o.w = d3 * invc;
                *(float4*)(dst + r) = o;
            }
        }
        redA[tid] = s1;
    }
    __syncthreads();
    if (tid < 128) {
        g_psum[b][it][m0 + tid] = redA[2 * tid] + redA[2 * tid + 1];
        if (!diag)
            g_psum[b][jt][n0 + tid] = redB[2 * tid] + redB[2 * tid + 1];
    }
}

// ============================================================================
// K4b: partial online max/sum-exp (round-10 4-chain form)
// ============================================================================
__global__ void k4b_partial() {
    const int b = blockIdx.z;
    const int chunk = blockIdx.y;
    const int m = blockIdx.x * 256 + threadIdx.x;

    float ps = 0.f;
#pragma unroll
    for (int t = 0; t < 32; t++) ps += g_psum[b][t][m];
    const float mean = ps * (1.0f / N);
    const float off = g_bmap[b][m] - mean * g_wmap[b][m];
    if (chunk == 0) g_off[b][m] = off;

    const int nbase = chunk * 256;
    float mx0 = -1e30f, mx1 = -1e30f, mx2 = -1e30f, mx3 = -1e30f;
    float s0 = 0.f, s1 = 0.f, s2 = 0.f, s3 = 0.f;

#define CHAIN(MX, S, L) { float sp = fmaxf((L) + off, 0.f); float z = (L) * sp; \
    if (z <= MX) { S += __expf(z - MX); } else { S = S * __expf(MX - z) + 1.f; MX = z; } }

#pragma unroll 2
    for (int r = 0; r < 256; r += 4) {
        float l0 = g_L[b][nbase + r + 0][m];
        float l1 = g_L[b][nbase + r + 1][m];
        float l2 = g_L[b][nbase + r + 2][m];
        float l3 = g_L[b][nbase + r + 3][m];
        CHAIN(mx0, s0, l0);
        CHAIN(mx1, s1, l1);
        CHAIN(mx2, s2, l2);
        CHAIN(mx3, s3, l3);
    }
#undef CHAIN
    float M = fmaxf(fmaxf(mx0, mx1), fmaxf(mx2, mx3));
    float S = s0 * __expf(mx0 - M) + s1 * __expf(mx1 - M)
            + s2 * __expf(mx2 - M) + s3 * __expf(mx3 - M);
    g_pmx[b][chunk][m] = M;
    g_psm[b][chunk][m] = S;
}

// ============================================================================
// K5 (mma.sync + cp.async, single-sync pipeline, 512 threads / 16 warps)
// warp grid 4(M)x4(N), 32x32 per warp. schedule:
//   MMA(i) | wait(i+1) | sync | issue(i+2) | transform(i+1) | sync
// ============================================================================
__global__ void __launch_bounds__(512, 1) k5_mma() {
    extern __shared__ char smem[];
    const uint32_t sb = smem_u32(smem);
    const int tid = threadIdx.x;
    const int wid = tid >> 5;
    const int lane = tid & 31;
    const int b = blockIdx.y;
    const int m0 = blockIdx.x * 128;

    float* p_off = (float*)(smem + K5_AUX);
    float* p_mx  = (float*)(smem + K5_AUX + 512);
    float* p_si  = (float*)(smem + K5_AUX + 1024);
    if (tid < 128) {
        int m = m0 + tid;
        p_off[tid] = g_off[b][m];
        float M = g_pmx[b][0][m];
        float S = g_psm[b][0][m];
#pragma unroll
        for (int t = 1; t < 16; t++) {
            float m2 = g_pmx[b][t][m], s2 = g_psm[b][t][m];
            float Mn = fmaxf(M, m2);
            S = S * __expf(M - Mn) + s2 * __expf(m2 - Mn);
            M = Mn;
        }
        p_mx[tid] = M;
        p_si[tid] = 1.0f / S;
    }

    const int wm = (wid & 3) * 32;        // 4 M-warps of 32 rows
    const int wn = (wid >> 2) * 32;       // 4 N-warps of 32 cols
    const uint32_t aoff = (uint32_t)((lane & 15) * (TP5 * 2) + (lane >> 4) * 16);
    const uint32_t boff = (uint32_t)((((lane >> 4) << 3) + (lane & 7)) * (TP5 * 2)
                                     + ((lane >> 3) & 1) * 16);

    // transform mapping: 512 threads, each 2 m-cols x 8 ks
    const int mm0 = (tid & 63) * 2;
    const int kk0 = (tid >> 6) * 8;

    float d[2][4][4];
#pragma unroll
    for (int mt = 0; mt < 2; mt++)
#pragma unroll
        for (int nt = 0; nt < 4; nt++)
#pragma unroll
            for (int q = 0; q < 4; q++) d[mt][nt][q] = 0.f;

#define K5_ISSUE(BUFI, NBASE) do {                                               \
        uint32_t abase = sb + (BUFI) * (2 * T5B);                                \
        for (int i = tid; i < 1024; i += 512) {                                  \
            int r = i >> 3, q = i & 7;                                           \
            cpa16(abase + r * (TP5 * 2) + q * 16,                                \
                  (const char*)&g_Vhi[b][r][NBASE] + q * 16);                    \
            cpa16(abase + T5B + r * (TP5 * 2) + q * 16,                          \
                  (const char*)&g_Vlo[b][r][NBASE] + q * 16);                    \
        }                                                                        \
        uint32_t lbase = sb + K5_LR + (BUFI) * 32768;                            \
        for (int i = tid; i < 2048; i += 512) {                                  \
            int kk = i >> 5, q = i & 31;                                         \
            cpa16(lbase + kk * 512 + q * 16,                                     \
                  (const char*)&g_L[b][NBASE + kk][m0] + q * 16);                \
        }                                                                        \
    } while (0)

#define K5_TRANSFORM(BUFI) do {                                                  \
        const float* Lr = (const float*)(smem + K5_LR + (BUFI) * 32768);         \
        uint32_t whi[2][4], wlo[2][4];                                           \
        _Pragma("unroll")                                                        \
        for (int j = 0; j < 2; j++)                                              \
            _Pragma("unroll")                                                    \
            for (int p = 0; p < 4; p++) { whi[j][p] = 0u; wlo[j][p] = 0u; }      \
        _Pragma("unroll")                                                        \
        for (int kk = 0; kk < 8; kk++) {                                         \
            float2 l2 = *(const float2*)(Lr + (kk0 + kk) * 128 + mm0);           \
            float ls[2] = {l2.x, l2.y};                                          \
            _Pragma("unroll")                                                    \
            for (int j = 0; j < 2; j++) {                                        \
                int m = mm0 + j;                                                 \
                float l = ls[j];                                                 \
                float sp = fmaxf(l + p_off[m], 0.f);                             \
                float a;                                                         \
                if (sp > 0.f)                                                    \
                    a = fmaxf(__expf(l * sp - p_mx[m]) * p_si[m], 1e-8f);        \
                else                                                             \
                    a = 1e-8f;                                                   \
                __nv_bfloat16 h = __float2bfloat16(a);                           \
                __nv_bfloat16 lo = __float2bfloat16(a - __bfloat162float(h));    \
                uint32_t sh = (uint32_t)(kk & 1) * 16;                           \
                whi[j][kk >> 1] |= (uint32_t)__bfloat16_as_ushort(h) << sh;      \
                wlo[j][kk >> 1] |= (uint32_t)__bfloat16_as_ushort(lo) << sh;     \
            }                                                                    \
        }                                                                        \
        char* bbase = smem + K5_B + (BUFI) * (2 * T5B);                          \
        _Pragma("unroll")                                                        \
        for (int j = 0; j < 2; j++) {                                            \
            uint4 vh; vh.x = whi[j][0]; vh.y = whi[j][1]; vh.z = whi[j][2]; vh.w = whi[j][3]; \
            uint4 vl; vl.x = wlo[j][0]; vl.y = wlo[j][1]; vl.z = wlo[j][2]; vl.w = wlo[j][3]; \
            *(uint4*)(bbase + (mm0 + j) * (TP5 * 2) + kk0 * 2) = vh;             \
            *(uint4*)(bbase + T5B + (mm0 + j) * (TP5 * 2) + kk0 * 2) = vl;       \
        }                                                                        \
    } while (0)

    // prologue
    K5_ISSUE(0, 0);
    CPA_COMMIT();
    CPA_WAIT0();
    __syncthreads();
    K5_ISSUE(1, 64);
    CPA_COMMIT();
    K5_TRANSFORM(0);
    __syncthreads();   // B[0] ready

    for (int ic = 0; ic < 64; ic++) {
        const int cur = ic & 1;
        const uint32_t abase = sb + cur * (2 * T5B);
        const uint32_t bbase = sb + K5_B + cur * (2 * T5B);
#pragma unroll
        for (int ks = 0; ks < 4; ks++) {
            const uint32_t kb2 = ks * 32;
            uint32_t ah[2][4], al[2][4], bh[2][4], bl[2][4];
#pragma unroll
            for (int mt = 0; mt < 2; mt++) {
                uint32_t rowb = (uint32_t)((wm + mt * 16) * (TP5 * 2)) + kb2 + aoff;
                ldsm_x4(ah[mt], abase + rowb);
                ldsm_x4(al[mt], abase + T5B + rowb);
            }
#pragma unroll
            for (int np = 0; np < 2; np++) {
                uint32_t rowb = (uint32_t)((wn + np * 16) * (TP5 * 2)) + kb2 + boff;
                ldsm_x4(bh[np], bbase + rowb);
                ldsm_x4(bl[np], bbase + T5B + rowb);
            }
#pragma unroll
            for (int mt = 0; mt < 2; mt++)
#pragma unroll
                for (int np = 0; np < 2; np++)
#pragma unroll
                    for (int sub = 0; sub < 2; sub++) {
                        const int nt = np * 2 + sub;
                        mma_bf16(d[mt][nt], ah[mt], &bh[np][sub * 2]);
                        mma_bf16(d[mt][nt], ah[mt], &bl[np][sub * 2]);
                        mma_bf16(d[mt][nt], al[mt], &bh[np][sub * 2]);
                    }
        }

        if (ic + 1 < 64) {
            CPA_WAIT0();        // chunk ic+1 data landed
            __syncthreads();    // MMA(ic) done; buffers of chunk ic free
            if (ic + 2 < 64) {
                K5_ISSUE(ic & 1, (ic + 2) * 64);   // in flight during transform
                CPA_COMMIT();
            }
            K5_TRANSFORM((ic + 1) & 1);
            __syncthreads();    // B[(ic+1)&1] ready
        }
    }
#undef K5_ISSUE
#undef K5_TRANSFORM

    __syncthreads();
    float* sD = (float*)smem;
    {
        const int g = lane >> 2, tg = lane & 3;
#pragma unroll
        for (int mt = 0; mt < 2; mt++) {
#pragma unroll
            for (int nt = 0; nt < 4; nt++) {
                int row0 = wm + mt * 16 + g;
                int col0 = wn + nt * 8 + 2 * tg;
                sD[row0 * 129 + col0]           = d[mt][nt][0];
                sD[row0 * 129 + col0 + 1]       = d[mt][nt][1];
                sD[(row0 + 8) * 129 + col0]     = d[mt][nt][2];
                sD[(row0 + 8) * 129 + col0 + 1] = d[mt][nt][3];
            }
        }
    }
    __syncthreads();
    {
        const int m = tid >> 2;
        const int cb = (tid & 3) * 32;
        uint32_t hibuf[16], lobuf[16];
#pragma unroll 8
        for (int u = 0; u < 16; u++) {
            float v0 = sD[(cb + 2 * u) * 129 + m];
            float v1 = sD[(cb + 2 * u + 1) * 129 + m];
            __nv_bfloat16 h0 = __float2bfloat16(v0);
            __nv_bfloat16 h1 = __float2bfloat16(v1);
            __nv_bfloat16 l0 = __float2bfloat16(v0 - __bfloat162float(h0));
            __nv_bfloat16 l1 = __float2bfloat16(v1 - __bfloat162float(h1));
            hibuf[u] = (uint32_t)__bfloat16_as_ushort(h0) | ((uint32_t)__bfloat16_as_ushort(h1) << 16);
            lobuf[u] = (uint32_t)__bfloat16_as_ushort(l0) | ((uint32_t)__bfloat16_as_ushort(l1) << 16);
        }
#pragma unroll
        for (int q = 0; q < 4; q++) {
            *(uint4*)&g_YTh[b][m0 + m][cb + q * 8] = *(uint4*)&hibuf[q * 4];
            *(uint4*)&g_YTl[b][m0 + m][cb + q * 8] = *(uint4*)&lobuf[q * 4];
        }
    }
}

// ============================================================================
// K6 (mma.sync + cp.async double buffer): conv3x3 implicit GEMM  [round-10]
// ============================================================================
__global__ void __launch_bounds__(256, 1) k6_mma(const float* __restrict__ linb,
                                                 const float* __restrict__ x,
                                                 float* __restrict__ out) {
    extern __shared__ char smem[];
    const uint32_t sb = smem_u32(smem);
    const int tid = threadIdx.x;
    const int wid = tid >> 5;
    const int lane = tid & 31;
    const int b = blockIdx.y;
    const int p0 = blockIdx.x * 128;

    const int wm = (wid & 1) * 64;
    const int wn = (wid >> 1) * 32;
    const uint32_t aoff = (uint32_t)((lane & 15) * (TP5 * 2) + (lane >> 4) * 16);
    const uint32_t boff = (uint32_t)((((lane >> 4) << 3) + (lane & 7)) * (TP5 * 2)
                                     + ((lane >> 3) & 1) * 16);

    float d[4][4][4];
#pragma unroll
    for (int mt = 0; mt < 4; mt++)
#pragma unroll
        for (int nt = 0; nt < 4; nt++)
#pragma unroll
            for (int q = 0; q < 4; q++) d[mt][nt][q] = 0.f;

#define K6_ISSUE(BUFI, T, CB) do {                                               \
        uint32_t base = sb + (BUFI) * (4 * T5B);                                 \
        for (int i = tid; i < 1024; i += 256) {                                  \
            int r = i >> 3, q = i & 7;                                           \
            cpa16(base + r * (TP5 * 2) + q * 16,                                 \
                  (const char*)&g_W6hi[r][(T) * 128 + (CB)] + q * 16);           \
            cpa16(base + T5B + r * (TP5 * 2) + q * 16,                           \
                  (const char*)&g_W6lo[r][(T) * 128 + (CB)] + q * 16);           \
        }                                                                        \
        {                                                                        \
            int dh = (T) / 3 - 1, dw = (T) % 3 - 1;                              \
            for (int i = tid; i < 1024; i += 256) {                              \
                int r = i >> 3, q = i & 7;                                       \
                int p = p0 + r;                                                  \
                int h = (p >> 6) + dh, w = (p & 63) + dw;                        \
                uint32_t dsth = base + 2 * T5B + r * (TP5 * 2) + q * 16;         \
                uint32_t dstl = base + 3 * T5B + r * (TP5 * 2) + q * 16;         \
                if (h >= 0 && h < HW && w >= 0 && w < HW) {                      \
                    int src = (h << 6) + w;                                      \
                    cpa16(dsth, (const char*)&g_YTh[b][src][CB] + q * 16);       \
                    cpa16(dstl, (const char*)&g_YTl[b][src][CB] + q * 16);       \
                } else {                                                         \
                    uint4 z = make_uint4(0u, 0u, 0u, 0u);                        \
                    *(uint4*)(smem + (BUFI) * (4 * T5B) + 2 * T5B + r * (TP5 * 2) + q * 16) = z; \
                    *(uint4*)(smem + (BUFI) * (4 * T5B) + 3 * T5B + r * (TP5 * 2) + q * 16) = z; \
                }                                                                \
            }                                                                    \
        }                                                                        \
    } while (0)

    K6_ISSUE(0, 0, 0);
    CPA_COMMIT();

    for (int ic = 0; ic < 18; ic++) {
        const int cur = ic & 1;
        if (ic + 1 < 18) {
            K6_ISSUE(cur ^ 1, (ic + 1) >> 1, ((ic + 1) & 1) * 64);
            CPA_COMMIT();
            CPA_WAIT1();
        } else {
            CPA_WAIT0();
        }
        __syncthreads();

        const uint32_t base = sb + cur * (4 * T5B);
#pragma unroll
        for (int ks = 0; ks < 4; ks++) {
            const uint32_t kb2 = ks * 32;
            uint32_t ah[4][4], al[4][4], bh[2][4], bl[2][4];
#pragma unroll
            for (int mt = 0; mt < 4; mt++) {
                uint32_t rowb = (uint32_t)((wm + mt * 16) * (TP5 * 2)) + kb2 + aoff;
                ldsm_x4(ah[mt], base + rowb);
                ldsm_x4(al[mt], base + T5B + rowb);
            }
#pragma unroll
            for (int np = 0; np < 2; np++) {
                uint32_t rowb = (uint32_t)((wn + np * 16) * (TP5 * 2)) + kb2 + boff;
                ldsm_x4(bh[np], base + 2 * T5B + rowb);
                ldsm_x4(bl[np], base + 3 * T5B + rowb);
            }
#pragma unroll
            for (int mt = 0; mt < 4; mt++)
#pragma unroll
                for (int np = 0; np < 2; np++)
#pragma unroll
                    for (int sub = 0; sub < 2; sub++) {
                        const int nt = np * 2 + sub;
                        mma_bf16(d[mt][nt], ah[mt], &bh[np][sub * 2]);
                        mma_bf16(d[mt][nt], ah[mt], &bl[np][sub * 2]);
                        mma_bf16(d[mt][nt], al[mt], &bh[np][sub * 2]);
                    }
        }
        __syncthreads();
    }
#undef K6_ISSUE

    {
        const int g = lane >> 2, tg = lane & 3;
#pragma unroll
        for (int mt = 0; mt < 4; mt++) {
            int o0 = wm + mt * 16 + g;
            float b0 = linb[o0];
            float b1 = linb[o0 + 8];
#pragma unroll
            for (int nt = 0; nt < 4; nt++) {
                int col0 = p0 + wn + nt * 8 + 2 * tg;
                size_t base0 = ((size_t)b * C + o0) * N + col0;
                size_t base1 = ((size_t)b * C + o0 + 8) * N + col0;
                float2 xr0 = *(const float2*)(x + base0);
                float2 xr1 = *(const float2*)(x + base1);
                float v00 = d[mt][nt][0] + b0;
                float v01 = d[mt][nt][1] + b0;
                float v10 = d[mt][nt][2] + b1;
                float v11 = d[mt][nt][3] + b1;
                v00 = (v00 >= 0.f) ? v00 : 0.2f * v00;
                v01 = (v01 >= 0.f) ? v01 : 0.2f * v01;
                v10 = (v10 >= 0.f) ? v10 : 0.2f * v10;
                v11 = (v11 >= 0.f) ? v11 : 0.2f * v11;
                float2 o0v; o0v.x = v00 + xr0.x; o0v.y = v01 + xr0.y;
                float2 o1v; o1v.x = v10 + xr1.x; o1v.y = v11 + xr1.y;
                *(float2*)(out + base0) = o0v;
                *(float2*)(out + base1) = o1v;
            }
        }
    }
}

// ============================================================================
extern "C" void kernel_launch(void* const* d_in, const int* in_sizes, int n_in,
                              void* d_out, int out_size) {
    const float* x     = (const float*)d_in[0];
    const float* q_w   = (const float*)d_in[1];
    const float* q_b   = (const float*)d_in[2];
    const float* v_w   = (const float*)d_in[3];
    const float* v_b   = (const float*)d_in[4];
    const float* lw1_w = (const float*)d_in[5];
    const float* lw1_b = (const float*)d_in[6];
    const float* lw2_w = (const float*)d_in[7];
    const float* lw2_b = (const float*)d_in[8];
    const float* bw1_w = (const float*)d_in[9];
    const float* bw1_b = (const float*)d_in[10];
    const float* bw2_w = (const float*)d_in[11];
    const float* bw2_b = (const float*)d_in[12];
    const float* lin_w = (const float*)d_in[13];
    const float* lin_b = (const float*)d_in[14];
    float* out = (float*)d_out;

    cudaFuncSetAttribute(k3_mma, cudaFuncAttributeMaxDynamicSharedMemorySize, K3_SMEM_BYTES);
    cudaFuncSetAttribute(k5_mma, cudaFuncAttributeMaxDynamicSharedMemorySize, K5_SMEM_BYTES);
    cudaFuncSetAttribute(k6_mma, cudaFuncAttributeMaxDynamicSharedMemorySize, K6_SMEM_BYTES);

    k6w_prep<<<(C * 9 * C + 255) / 256, 256>>>(lin_w);
    k1_qv<<<dim3(N / 128, BATCH, 2), 256>>>(x, q_w, q_b, v_w, v_b);
    k1t_transpose<<<dim3(N / 32, C / 32, BATCH), 256>>>();
    k2_heads<<<dim3(N / 256, BATCH, 2), 256>>>(lw1_w, lw1_b, lw2_w, lw2_b,
                                               bw1_w, bw1_b, bw2_w, bw2_b);
    k3_mma<<<dim3(528, BATCH), 256, K3_SMEM_BYTES>>>();
    k4b_partial<<<dim3(16, 16, BATCH), 256>>>();
    k5_mma<<<dim3(N / 128, BATCH), 512, K5_SMEM_BYTES>>>();
    k6_mma<<<dim3(N / 128, BATCH), 256, K6_SMEM_BYTES>>>(lin_b, x, out);
}